// round 1
// baseline (speedup 1.0000x reference)
#include <cuda_runtime.h>

// LearnableMSNonLocalKernelDCT: phi = (lam ⊙ (rho @ C^T)) @ C, rank-256 form.
// B=1024, N=4096, R=256.
//
// Pipeline (all device-side, graph-capturable, no allocations):
//   1. k_build_C : Cs[k][n] = C[k+1][n], replicating the reference's fp32
//                  rounding of theta, cos evaluated via cospif + correction.
//   2. k_gemm1   : part[s] = rho @ Cs^T  (split-K=2, 64x64 tiles, f32x2 FMA)
//   3. k_reduce  : Al = (part0+part1) * lam[k]
//   4. k_gemm2   : phi = Al @ Cs        (64x128 tiles, f32x2 FMA)

#define NB 1024
#define NG 4096
#define RR 256

__device__ __align__(16) float g_C[RR * NG];        // 4 MB: Cs[k][n], k=0..255 <-> DCT row k+1
__device__ __align__(16) float g_part[2][NB * RR];  // 2 MB: split-K partials of rho @ Cs^T
__device__ __align__(16) float g_Al[NB * RR];       // 1 MB: lam-scaled A

// Packed fp32x2 helpers (B300 FFMA2: 2x fp32 FMA per instruction)
#define PK2(out, lo, hi) \
    asm("mov.b64 %0, {%1, %2};" : "=l"(out) : "r"(__float_as_uint(lo)), "r"(__float_as_uint(hi)))
#define FFMA2(d, a, b, c) \
    asm("fma.rn.f32x2 %0, %1, %2, %3;" : "=l"(d) : "l"(a), "l"(b), "l"(c))
#define UPK2(lo, hi, v) do { \
    unsigned int _l, _h; \
    asm("mov.b64 {%0, %1}, %2;" : "=r"(_l), "=r"(_h) : "l"(v)); \
    (lo) = __uint_as_float(_l); (hi) = __uint_as_float(_h); } while (0)

// ---------------------------------------------------------------------------
// Build Cs. Reference computes (all fp32):
//   theta = ((pi_f * (2n+1)) * k) / 8192 ;  C = cos(theta) * sqrt(2/4096)
// We reproduce theta's exact fp32 rounding chain, then evaluate cos(theta_fp32)
// accurately (independent of fast-math) as:
//   theta_fp32 = pi*m/8192 + e,  m = (2n+1)*(k+1)  (exact integer < 2^24)
//   cos(theta_fp32) ~= cospi(mr/8192) - e * sinpi(mr/8192),  mr = m mod 16384
// e <= ~2e-4 rad, so the dropped e^2/2 term is < 2e-8: far below tolerance.
// ---------------------------------------------------------------------------
__global__ void k_build_C() {
    int idx = blockIdx.x * 256 + threadIdx.x;      // 0 .. RR*NG-1
    int k = idx >> 12;                              // 0..255
    int n = idx & (NG - 1);                         // 0..4095
    int kk = k + 1;                                 // DCT row 1..256

    float t1 = 2.0f * (float)n + 1.0f;              // exact
    float t2 = 3.14159274101257324f * t1;           // fl(pi_f * t1)
    float t3 = t2 * (float)kk;                      // fl(.. * k)
    float th = t3 * (1.0f / 8192.0f);               // exact /8192

    int m = (2 * n + 1) * kk;                       // exact, < 2^24
    float x = (float)(m & 16383) * (1.0f / 8192.0f);
    double e = (double)th - 3.14159265358979323846 * (double)m * (1.0 / 8192.0);
    float c = cospif(x) - (float)e * sinpif(x);
    g_C[idx] = c * sqrtf(2.0f / 4096.0f);
}

// ---------------------------------------------------------------------------
// GEMM1 (TN): part[z][m][kdct] = sum_{n in z-slice} rho[m][n] * Cs[kdct][n]
// Tiles: BM=64, BN=64, BK=32, split-K=2 -> grid (4, 16, 2) = 128 CTAs.
// 256 threads, 4x4 micro-tile per thread, N-dim packed into f32x2 pairs.
// ---------------------------------------------------------------------------
__global__ void __launch_bounds__(256) k_gemm1(const float* __restrict__ rho) {
    __shared__ __align__(16) float As[32][68];  // [k][m], pad 68 -> conflict-free transpose
    __shared__ __align__(16) float Bs[32][68];  // [k][n]

    const int tid = threadIdx.x;
    const int tx = tid & 15;        // n: 4 outputs
    const int ty = tid >> 4;        // m: 4 outputs
    const int m0 = blockIdx.y * 64;
    const int n0 = blockIdx.x * 64;
    const int k0 = blockIdx.z * 2048;

    unsigned long long acc[4][2];
#pragma unroll
    for (int i = 0; i < 4; i++) { acc[i][0] = 0ull; acc[i][1] = 0ull; }

    for (int kt = 0; kt < 2048; kt += 32) {
#pragma unroll
        for (int t = 0; t < 2; t++) {
            int id = tid + t * 256;             // 0..511
            int row = id >> 3;                  // 0..63
            int c4 = id & 7;                    // float4 index along k
            float4 va = *(const float4*)(rho + (size_t)(m0 + row) * NG + (k0 + kt) + c4 * 4);
            As[c4 * 4 + 0][row] = va.x; As[c4 * 4 + 1][row] = va.y;
            As[c4 * 4 + 2][row] = va.z; As[c4 * 4 + 3][row] = va.w;
            float4 vb = *(const float4*)(g_C + (size_t)(n0 + row) * NG + (k0 + kt) + c4 * 4);
            Bs[c4 * 4 + 0][row] = vb.x; Bs[c4 * 4 + 1][row] = vb.y;
            Bs[c4 * 4 + 2][row] = vb.z; Bs[c4 * 4 + 3][row] = vb.w;
        }
        __syncthreads();
#pragma unroll
        for (int kk2 = 0; kk2 < 32; kk2++) {
            float4 a4 = *(const float4*)&As[kk2][ty * 4];
            const unsigned long long* bp = (const unsigned long long*)&Bs[kk2][tx * 4];
            unsigned long long b01 = bp[0], b23 = bp[1];
            float av[4] = {a4.x, a4.y, a4.z, a4.w};
#pragma unroll
            for (int i = 0; i < 4; i++) {
                unsigned long long ar;
                PK2(ar, av[i], av[i]);
                FFMA2(acc[i][0], ar, b01, acc[i][0]);
                FFMA2(acc[i][1], ar, b23, acc[i][1]);
            }
        }
        __syncthreads();
    }

    float* outp = g_part[blockIdx.z];
#pragma unroll
    for (int i = 0; i < 4; i++) {
        float f0, f1, f2, f3;
        UPK2(f0, f1, acc[i][0]);
        UPK2(f2, f3, acc[i][1]);
        *(float4*)(outp + (size_t)(m0 + ty * 4 + i) * RR + n0 + tx * 4) =
            make_float4(f0, f1, f2, f3);
    }
}

// Al[m][k] = (part0 + part1) * lam[k]   (lam[k] = ms_kernel[k], k -> DCT row k+1)
__global__ void k_reduce(const float* __restrict__ lam) {
    int i = blockIdx.x * 256 + threadIdx.x;
    g_Al[i] = (g_part[0][i] + g_part[1][i]) * lam[i & (RR - 1)];
}

// ---------------------------------------------------------------------------
// GEMM2 (NN): phi[m][n] = sum_k Al[m][k] * Cs[k][n]
// Tiles: BM=64, BN=128, BK=32 -> grid (32, 16) = 512 CTAs.
// 256 threads, 4x8 micro-tile per thread.
// ---------------------------------------------------------------------------
__global__ void __launch_bounds__(256) k_gemm2(float* __restrict__ phi) {
    __shared__ __align__(16) float As[32][68];   // [k][m] transposed
    __shared__ __align__(16) float Bs[32][128];  // [k][n] direct

    const int tid = threadIdx.x;
    const int tx = tid & 15;        // n: 8 outputs
    const int ty = tid >> 4;        // m: 4 outputs
    const int m0 = blockIdx.y * 64;
    const int n0 = blockIdx.x * 128;

    unsigned long long acc[4][4];
#pragma unroll
    for (int i = 0; i < 4; i++)
#pragma unroll
        for (int j = 0; j < 4; j++) acc[i][j] = 0ull;

    for (int kt = 0; kt < RR; kt += 32) {
#pragma unroll
        for (int t = 0; t < 2; t++) {
            int id = tid + t * 256;
            int row = id >> 3, c4 = id & 7;
            float4 va = *(const float4*)(g_Al + (size_t)(m0 + row) * RR + kt + c4 * 4);
            As[c4 * 4 + 0][row] = va.x; As[c4 * 4 + 1][row] = va.y;
            As[c4 * 4 + 2][row] = va.z; As[c4 * 4 + 3][row] = va.w;
        }
#pragma unroll
        for (int t = 0; t < 4; t++) {
            int id = tid + t * 256;             // 0..1023
            int row = id >> 5;                  // 0..31 (k)
            int c4 = id & 31;                   // float4 along n
            *(float4*)&Bs[row][c4 * 4] =
                *(const float4*)(g_C + (size_t)(kt + row) * NG + n0 + c4 * 4);
        }
        __syncthreads();
#pragma unroll
        for (int kk2 = 0; kk2 < 32; kk2++) {
            float4 a4 = *(const float4*)&As[kk2][ty * 4];
            const unsigned long long* bp = (const unsigned long long*)&Bs[kk2][tx * 8];
            unsigned long long b[4] = {bp[0], bp[1], bp[2], bp[3]};
            float av[4] = {a4.x, a4.y, a4.z, a4.w};
#pragma unroll
            for (int i = 0; i < 4; i++) {
                unsigned long long ar;
                PK2(ar, av[i], av[i]);
#pragma unroll
                for (int j = 0; j < 4; j++) FFMA2(acc[i][j], ar, b[j], acc[i][j]);
            }
        }
        __syncthreads();
    }

#pragma unroll
    for (int i = 0; i < 4; i++) {
        float f[8];
        UPK2(f[0], f[1], acc[i][0]); UPK2(f[2], f[3], acc[i][1]);
        UPK2(f[4], f[5], acc[i][2]); UPK2(f[6], f[7], acc[i][3]);
        float* dst = phi + (size_t)(m0 + ty * 4 + i) * NG + n0 + tx * 8;
        *(float4*)dst = make_float4(f[0], f[1], f[2], f[3]);
        *(float4*)(dst + 4) = make_float4(f[4], f[5], f[6], f[7]);
    }
}

extern "C" void kernel_launch(void* const* d_in, const int* in_sizes, int n_in,
                              void* d_out, int out_size) {
    const float* rho = (const float*)d_in[0];        // [1024, 4096]
    const float* lam = (const float*)d_in[1];        // [256]
    float* phi = (float*)d_out;                      // [1024, 4096]
    (void)in_sizes; (void)n_in; (void)out_size;

    k_build_C<<<(RR * NG) / 256, 256>>>();
    k_gemm1<<<dim3(4, 16, 2), 256>>>(rho);
    k_reduce<<<(NB * RR) / 256, 256>>>(lam);
    k_gemm2<<<dim3(32, 16), 256>>>(phi);
}

// round 3
// speedup vs baseline: 2.3072x; 2.3072x over previous
#include <cuda_runtime.h>
#include <cuda_bf16.h>
#include <cstdint>

// phi = (lam ⊙ (rho @ Cs^T)) @ Cs, rank-256. B=1024, N=4096, R=256.
// Base-ISA tensor path: mma.sync.m16n8k16.bf16 with hi/lo split (3 MMAs),
// cp.async double-buffered SMEM, ldmatrix fragments. fp32 accumulation.
//
//  1. k_build_C   : g_C_h/l [256][4096]  bf16 hi/lo of Cs (exact-rounding replica)
//  2. k_build_CT  : g_CT_h/l[4096][256]  bf16 hi/lo of Cs^T
//  3. k_split_rho : g_rho_h/l = bf16 hi/lo of rho
//  4. k_gemm x8 splits: g_part[z] = rho @ Cs^T   (M128xN128 tiles)
//  5. k_reduce    : Al = (sum_z part)*lam -> g_Al_h/l bf16
//  6. k_gemm      : phi = Al @ Cs^T^T  (B = CT planes, K=256)

#define NB 1024
#define NG 4096
#define RR 256
#define SPLITS 8

__device__ __align__(16) __nv_bfloat16 g_C_h[RR * NG];
__device__ __align__(16) __nv_bfloat16 g_C_l[RR * NG];
__device__ __align__(16) __nv_bfloat16 g_CT_h[NG * RR];
__device__ __align__(16) __nv_bfloat16 g_CT_l[NG * RR];
__device__ __align__(16) __nv_bfloat16 g_rho_h[NB * NG];
__device__ __align__(16) __nv_bfloat16 g_rho_l[NB * NG];
__device__ __align__(16) __nv_bfloat16 g_Al_h[NB * RR];
__device__ __align__(16) __nv_bfloat16 g_Al_l[NB * RR];
__device__ __align__(16) float g_part[SPLITS * NB * RR];   // 8 MB

// ----------------------------- PTX helpers ---------------------------------
__device__ __forceinline__ uint32_t smem_u32(const void* p) {
    uint32_t a;
    asm("{ .reg .u64 t; cvta.to.shared.u64 t, %1; cvt.u32.u64 %0, t; }" : "=r"(a) : "l"(p));
    return a;
}
#define CP16(dst, src) \
    asm volatile("cp.async.cg.shared.global [%0], [%1], 16;" :: "r"(dst), "l"(src))
#define CP_COMMIT() asm volatile("cp.async.commit_group;" ::: "memory")
#define CP_WAIT1()  asm volatile("cp.async.wait_group 1;" ::: "memory")
#define LDSM4(r, a) \
    asm volatile("ldmatrix.sync.aligned.m8n8.x4.shared.b16 {%0,%1,%2,%3}, [%4];" \
        : "=r"((r)[0]), "=r"((r)[1]), "=r"((r)[2]), "=r"((r)[3]) : "r"(a))
#define MMA(c, a, b0, b1) \
    asm volatile("mma.sync.aligned.m16n8k16.row.col.f32.bf16.bf16.f32 " \
        "{%0,%1,%2,%3},{%4,%5,%6,%7},{%8,%9},{%0,%1,%2,%3};" \
        : "+f"((c)[0]), "+f"((c)[1]), "+f"((c)[2]), "+f"((c)[3]) \
        : "r"((a)[0]), "r"((a)[1]), "r"((a)[2]), "r"((a)[3]), "r"(b0), "r"(b1))

// --------------------- build Cs (exact fp32-rounding replica) ---------------
__device__ __forceinline__ float dct_entry(int n, int kk) {
    float t1 = 2.0f * (float)n + 1.0f;
    float t2 = 3.14159274101257324f * t1;
    float t3 = t2 * (float)kk;
    float th = t3 * (1.0f / 8192.0f);
    int m = (2 * n + 1) * kk;
    float x = (float)(m & 16383) * (1.0f / 8192.0f);
    double e = (double)th - 3.14159265358979323846 * (double)m * (1.0 / 8192.0);
    float c = cospif(x) - (float)e * sinpif(x);
    return c * sqrtf(2.0f / 4096.0f);
}
__device__ __forceinline__ void split_store(__nv_bfloat16* ph, __nv_bfloat16* pl,
                                            int idx, float v) {
    __nv_bfloat16 h = __float2bfloat16(v);
    ph[idx] = h;
    pl[idx] = __float2bfloat16(v - __bfloat162float(h));
}
__global__ void k_build_C() {
    int idx = blockIdx.x * 256 + threadIdx.x;
    int k = idx >> 12, n = idx & (NG - 1);
    split_store(g_C_h, g_C_l, idx, dct_entry(n, k + 1));
}
__global__ void k_build_CT() {
    int idx = blockIdx.x * 256 + threadIdx.x;
    int n = idx >> 8, k = idx & (RR - 1);
    split_store(g_CT_h, g_CT_l, idx, dct_entry(n, k + 1));
}
__global__ void k_split_rho(const float* __restrict__ rho) {
    int i = blockIdx.x * 256 + threadIdx.x;          // float4 index
    float4 v = *(const float4*)(rho + (size_t)i * 4);
    split_store(g_rho_h, g_rho_l, i * 4 + 0, v.x);
    split_store(g_rho_h, g_rho_l, i * 4 + 1, v.y);
    split_store(g_rho_h, g_rho_l, i * 4 + 2, v.z);
    split_store(g_rho_h, g_rho_l, i * 4 + 3, v.w);
}

// --------------- unified HMMA GEMM: out[M,N] = A[M,K] @ B[N,K]^T ------------
// CTA tile M=128, N=128, K-chunk 32. 8 warps: warp (m 4) x (n 2), warp tile 32x64.
// SMEM per stage: 4 planes (Ah, Al, Bh, Bl) of 128 rows x 80B (32 bf16 + pad).
#define PITCH   80
#define PLANE_B (128 * PITCH)       // 10240
#define STAGE_B (4 * PLANE_B)       // 40960
#define SMEM_SZ (2 * STAGE_B)       // 81920

__global__ void __launch_bounds__(256) k_gemm(
    const __nv_bfloat16* __restrict__ Ah, const __nv_bfloat16* __restrict__ Alo,
    const __nv_bfloat16* __restrict__ Bh, const __nv_bfloat16* __restrict__ Blo,
    float* __restrict__ out, int lda, int ldb, int ldo,
    int kper, long long zstride)
{
    extern __shared__ char smem[];
    const uint32_t sb = smem_u32(smem);
    const int tid = threadIdx.x;
    const int lane = tid & 31;
    const int warp_m = (tid >> 5) & 3;
    const int warp_n = tid >> 7;
    const int m0 = blockIdx.x * 128;
    const int n0 = blockIdx.y * 128;
    const int k0 = blockIdx.z * kper;
    const int NC = kper >> 5;
    out += (long long)blockIdx.z * zstride;

    // cp.async per-thread mapping: 2 iters x (row = id>>2, c16 = id&3) per plane
    const int r0 = tid >> 2, c0 = tid & 3;
    const int r1 = (tid + 256) >> 2, c1 = tid & 3;
    const long long aoff0 = (long long)(m0 + r0) * lda, aoff1 = (long long)(m0 + r1) * lda;
    const long long boff0 = (long long)(n0 + r0) * ldb, boff1 = (long long)(n0 + r1) * ldb;

#define ISSUE_CHUNK(i) do { \
    int kb = k0 + (i) * 32; \
    uint32_t st = sb + ((i) & 1) * STAGE_B; \
    CP16(st + 0*PLANE_B + r0*PITCH + c0*16, (const char*)Ah  + (aoff0 + kb + c0*8)*2); \
    CP16(st + 0*PLANE_B + r1*PITCH + c1*16, (const char*)Ah  + (aoff1 + kb + c1*8)*2); \
    CP16(st + 1*PLANE_B + r0*PITCH + c0*16, (const char*)Alo + (aoff0 + kb + c0*8)*2); \
    CP16(st + 1*PLANE_B + r1*PITCH + c1*16, (const char*)Alo + (aoff1 + kb + c1*8)*2); \
    CP16(st + 2*PLANE_B + r0*PITCH + c0*16, (const char*)Bh  + (boff0 + kb + c0*8)*2); \
    CP16(st + 2*PLANE_B + r1*PITCH + c1*16, (const char*)Bh  + (boff1 + kb + c1*8)*2); \
    CP16(st + 3*PLANE_B + r0*PITCH + c0*16, (const char*)Blo + (boff0 + kb + c0*8)*2); \
    CP16(st + 3*PLANE_B + r1*PITCH + c1*16, (const char*)Blo + (boff1 + kb + c1*8)*2); \
    } while (0)

    float acc[2][8][4];
#pragma unroll
    for (int mt = 0; mt < 2; mt++)
#pragma unroll
        for (int j = 0; j < 8; j++)
#pragma unroll
            for (int q = 0; q < 4; q++) acc[mt][j][q] = 0.f;

    // ldmatrix lane address components (PITCH-row layout, conflict-free)
    const uint32_t a_lane = (uint32_t)(((lane & 7) + ((lane >> 3) & 1) * 8) * PITCH
                                       + (lane >> 4) * 16);
    const uint32_t b_lane = (uint32_t)(((lane & 7) + (lane >> 4) * 8) * PITCH
                                       + ((lane >> 3) & 1) * 16);

    ISSUE_CHUNK(0);
    CP_COMMIT();

    for (int i = 0; i < NC; i++) {
        if (i + 1 < NC) ISSUE_CHUNK(i + 1);
        CP_COMMIT();
        CP_WAIT1();
        __syncthreads();

        const uint32_t st = sb + (i & 1) * STAGE_B;
#pragma unroll
        for (int s = 0; s < 2; s++) {
            uint32_t ah[2][4], al[2][4], bh[4][4], bl[4][4];
#pragma unroll
            for (int mt = 0; mt < 2; mt++) {
                uint32_t aa = st + (uint32_t)((warp_m * 32 + mt * 16) * PITCH + s * 32) + a_lane;
                LDSM4(ah[mt], aa);
                LDSM4(al[mt], aa + PLANE_B);
            }
#pragma unroll
            for (int nt = 0; nt < 4; nt++) {
                uint32_t ba = st + 2 * PLANE_B
                            + (uint32_t)((warp_n * 64 + nt * 16) * PITCH + s * 32) + b_lane;
                LDSM4(bh[nt], ba);
                LDSM4(bl[nt], ba + PLANE_B);
            }
#pragma unroll
            for (int mt = 0; mt < 2; mt++)
#pragma unroll
                for (int j = 0; j < 8; j++) {
                    uint32_t bjh0 = bh[j >> 1][(j & 1) * 2], bjh1 = bh[j >> 1][(j & 1) * 2 + 1];
                    uint32_t bjl0 = bl[j >> 1][(j & 1) * 2], bjl1 = bl[j >> 1][(j & 1) * 2 + 1];
                    MMA(acc[mt][j], ah[mt], bjh0, bjh1);
                    MMA(acc[mt][j], ah[mt], bjl0, bjl1);
                    MMA(acc[mt][j], al[mt], bjh0, bjh1);
                }
        }
        __syncthreads();
    }

    // epilogue: standard m16n8 accumulator layout
    const int mbase = m0 + warp_m * 32;
    const int nbase = n0 + warp_n * 64;
#pragma unroll
    for (int mt = 0; mt < 2; mt++)
#pragma unroll
        for (int j = 0; j < 8; j++) {
            float* d = out + (long long)(mbase + mt * 16 + (lane >> 2)) * ldo
                           + nbase + j * 8 + (lane & 3) * 2;
            d[0] = acc[mt][j][0];
            d[1] = acc[mt][j][1];
            d[(long long)ldo * 8]     = acc[mt][j][2];
            d[(long long)ldo * 8 + 1] = acc[mt][j][3];
        }
}

// -------- reduce partials + lam scale -> Al bf16 hi/lo ----------------------
__global__ void k_reduce(const float* __restrict__ lam) {
    int i = blockIdx.x * 256 + threadIdx.x;          // float4 index over NB*RR/4
    float4 s = make_float4(0.f, 0.f, 0.f, 0.f);
#pragma unroll
    for (int z = 0; z < SPLITS; z++) {
        float4 p = *(const float4*)(g_part + (long long)z * NB * RR + i * 4);
        s.x += p.x; s.y += p.y; s.z += p.z; s.w += p.w;
    }
    int k = (i * 4) & (RR - 1);
    s.x *= lam[k]; s.y *= lam[k + 1]; s.z *= lam[k + 2]; s.w *= lam[k + 3];
    split_store(g_Al_h, g_Al_l, i * 4 + 0, s.x);
    split_store(g_Al_h, g_Al_l, i * 4 + 1, s.y);
    split_store(g_Al_h, g_Al_l, i * 4 + 2, s.z);
    split_store(g_Al_h, g_Al_l, i * 4 + 3, s.w);
}

extern "C" void kernel_launch(void* const* d_in, const int* in_sizes, int n_in,
                              void* d_out, int out_size) {
    const float* rho = (const float*)d_in[0];        // [1024, 4096]
    const float* lam = (const float*)d_in[1];        // [256]
    float* phi = (float*)d_out;                      // [1024, 4096]
    (void)in_sizes; (void)n_in; (void)out_size;

    __nv_bfloat16 *pCh, *pCl, *pCTh, *pCTl, *pRh, *pRl, *pAh, *pAl;
    float* pPart;
    cudaGetSymbolAddress((void**)&pCh, g_C_h);
    cudaGetSymbolAddress((void**)&pCl, g_C_l);
    cudaGetSymbolAddress((void**)&pCTh, g_CT_h);
    cudaGetSymbolAddress((void**)&pCTl, g_CT_l);
    cudaGetSymbolAddress((void**)&pRh, g_rho_h);
    cudaGetSymbolAddress((void**)&pRl, g_rho_l);
    cudaGetSymbolAddress((void**)&pAh, g_Al_h);
    cudaGetSymbolAddress((void**)&pAl, g_Al_l);
    cudaGetSymbolAddress((void**)&pPart, g_part);
    cudaFuncSetAttribute(k_gemm, cudaFuncAttributeMaxDynamicSharedMemorySize, SMEM_SZ);

    k_build_C<<<(RR * NG) / 256, 256>>>();
    k_build_CT<<<(NG * RR) / 256, 256>>>();
    k_split_rho<<<(NB * NG) / 1024, 256>>>(rho);
    // GEMM1: part[z] = rho @ Cs^T   (M=1024, N=256, K=4096, split-K=8)
    k_gemm<<<dim3(8, 2, SPLITS), 256, SMEM_SZ>>>(pRh, pRl, pCh, pCl, pPart,
                                                 NG, NG, RR, NG / SPLITS,
                                                 (long long)NB * RR);
    k_reduce<<<(NB * RR) / 1024, 256>>>(lam);
    // GEMM2: phi = Al @ CT^T        (M=1024, N=4096, K=256)
    k_gemm<<<dim3(8, 32, 1), 256, SMEM_SZ>>>(pAh, pAl, pCTh, pCTl, phi,
                                             RR, RR, NG, RR, 0);
}

// round 4
// speedup vs baseline: 2.6644x; 1.1548x over previous
#include <cuda_runtime.h>
#include <cuda_bf16.h>
#include <cstdint>

// phi = (lam ⊙ (rho @ Cs^T)) @ Cs, rank-256. B=1024, N=4096, R=256.
// HMMA m16n8k16 bf16 hi/lo split (3 MMAs), cp.async double-buffered.
// R4: trig via 16K LUT (MUFU once per table entry), C+CT built in one pass
//     with smem transpose; split-K=16 and 2 CTAs/SM for the GEMMs.

#define NB 1024
#define NG 4096
#define RR 256
#define SPLITS 16

__device__ __align__(16) __nv_bfloat16 g_C_h[RR * NG];
__device__ __align__(16) __nv_bfloat16 g_C_l[RR * NG];
__device__ __align__(16) __nv_bfloat16 g_CT_h[NG * RR];
__device__ __align__(16) __nv_bfloat16 g_CT_l[NG * RR];
__device__ __align__(16) __nv_bfloat16 g_rho_h[NB * NG];
__device__ __align__(16) __nv_bfloat16 g_rho_l[NB * NG];
__device__ __align__(16) __nv_bfloat16 g_Al_h[NB * RR];
__device__ __align__(16) __nv_bfloat16 g_Al_l[NB * RR];
__device__ __align__(16) float g_part[SPLITS * NB * RR];   // 16 MB
__device__ __align__(16) float g_lut_c[16384];             // cospi(j/8192)*scale
__device__ __align__(16) float g_lut_s[16384];             // sinpi(j/8192)*scale

// ----------------------------- PTX helpers ---------------------------------
__device__ __forceinline__ uint32_t smem_u32(const void* p) {
    uint32_t a;
    asm("{ .reg .u64 t; cvta.to.shared.u64 t, %1; cvt.u32.u64 %0, t; }" : "=r"(a) : "l"(p));
    return a;
}
#define CP16(dst, src) \
    asm volatile("cp.async.cg.shared.global [%0], [%1], 16;" :: "r"(dst), "l"(src))
#define CP_COMMIT() asm volatile("cp.async.commit_group;" ::: "memory")
#define CP_WAIT1()  asm volatile("cp.async.wait_group 1;" ::: "memory")
#define LDSM4(r, a) \
    asm volatile("ldmatrix.sync.aligned.m8n8.x4.shared.b16 {%0,%1,%2,%3}, [%4];" \
        : "=r"((r)[0]), "=r"((r)[1]), "=r"((r)[2]), "=r"((r)[3]) : "r"(a))
#define MMA(c, a, b0, b1) \
    asm volatile("mma.sync.aligned.m16n8k16.row.col.f32.bf16.bf16.f32 " \
        "{%0,%1,%2,%3},{%4,%5,%6,%7},{%8,%9},{%0,%1,%2,%3};" \
        : "+f"((c)[0]), "+f"((c)[1]), "+f"((c)[2]), "+f"((c)[3]) \
        : "r"((a)[0]), "r"((a)[1]), "r"((a)[2]), "r"((a)[3]), "r"(b0), "r"(b1))

// ------------------------------- LUT build ----------------------------------
__global__ void k_lut() {
    int j = blockIdx.x * 256 + threadIdx.x;        // 0..16383
    float x = (float)j * (1.0f / 8192.0f);
    float sc = sqrtf(2.0f / 4096.0f);
    g_lut_c[j] = cospif(x) * sc;
    g_lut_s[j] = sinpif(x) * sc;
}

// ---------------- build C and CT planes in one pass -------------------------
// Reference fp32 rounding chain for theta is replicated exactly:
//   th = fl(fl(fl(pi_f*(2n+1))*kk)/8192);  entry = cos(th)*sqrt(2/4096)
// cos(th) = cospi(m/8192) - e*sinpi(m/8192) + O(e^2),  m=(2n+1)*kk < 2^21,
//   e = th - pi*m/8192 computed fp32-exactly via fma + 2-term pi.
#define PI_F  3.14159274101257324f
#define PI_LO (-8.742277657347586e-8f)

__device__ __forceinline__ void dct_hi_lo(int n, int kk, __nv_bfloat16& h, __nv_bfloat16& l) {
    float t1 = 2.0f * (float)n + 1.0f;
    float t2 = PI_F * t1;
    float t3 = t2 * (float)kk;
    float th = t3 * (1.0f / 8192.0f);
    int m = (2 * n + 1) * kk;
    float x = (float)m * (1.0f / 8192.0f);          // exact (m < 2^21)
    float e = fmaf(-PI_F, x, th) - PI_LO * x;       // th - pi*x
    int j = m & 16383;
    float v = __ldg(&g_lut_c[j]) - e * __ldg(&g_lut_s[j]);
    h = __float2bfloat16(v);
    l = __float2bfloat16(v - __bfloat162float(h));
}

__global__ void k_build() {          // grid (128, 8), block (32, 8)
    __shared__ __nv_bfloat16 sh[32][33], sl[32][33];
    const int tx = threadIdx.x, ty = threadIdx.y;
    const int n0 = blockIdx.x * 32, k0 = blockIdx.y * 32;
#pragma unroll
    for (int i = 0; i < 4; i++) {
        int kl = ty + i * 8;                       // local k
        __nv_bfloat16 h, l;
        dct_hi_lo(n0 + tx, k0 + kl + 1, h, l);
        g_C_h[(k0 + kl) * NG + n0 + tx] = h;
        g_C_l[(k0 + kl) * NG + n0 + tx] = l;
        sh[kl][tx] = h; sl[kl][tx] = l;
    }
    __syncthreads();
#pragma unroll
    for (int i = 0; i < 4; i++) {
        int nl = ty + i * 8;                       // local n
        g_CT_h[(n0 + nl) * RR + k0 + tx] = sh[tx][nl];
        g_CT_l[(n0 + nl) * RR + k0 + tx] = sl[tx][nl];
    }
}

__device__ __forceinline__ void split_store(__nv_bfloat16* ph, __nv_bfloat16* pl,
                                            int idx, float v) {
    __nv_bfloat16 h = __float2bfloat16(v);
    ph[idx] = h;
    pl[idx] = __float2bfloat16(v - __bfloat162float(h));
}
__global__ void k_split_rho(const float* __restrict__ rho) {
    int i = blockIdx.x * 256 + threadIdx.x;
    float4 v = *(const float4*)(rho + (size_t)i * 4);
    split_store(g_rho_h, g_rho_l, i * 4 + 0, v.x);
    split_store(g_rho_h, g_rho_l, i * 4 + 1, v.y);
    split_store(g_rho_h, g_rho_l, i * 4 + 2, v.z);
    split_store(g_rho_h, g_rho_l, i * 4 + 3, v.w);
}

// --------------- unified HMMA GEMM: out[M,N] = A[M,K] @ B[N,K]^T ------------
#define PITCH   80
#define PLANE_B (128 * PITCH)
#define STAGE_B (4 * PLANE_B)
#define SMEM_SZ (2 * STAGE_B)       // 80 KB

__global__ void __launch_bounds__(256, 2) k_gemm(
    const __nv_bfloat16* __restrict__ Ah, const __nv_bfloat16* __restrict__ Alo,
    const __nv_bfloat16* __restrict__ Bh, const __nv_bfloat16* __restrict__ Blo,
    float* __restrict__ out, int lda, int ldb, int ldo,
    int kper, long long zstride)
{
    extern __shared__ char smem[];
    const uint32_t sb = smem_u32(smem);
    const int tid = threadIdx.x;
    const int lane = tid & 31;
    const int warp_m = (tid >> 5) & 3;
    const int warp_n = tid >> 7;
    const int m0 = blockIdx.x * 128;
    const int n0 = blockIdx.y * 128;
    const int k0 = blockIdx.z * kper;
    const int NC = kper >> 5;
    out += (long long)blockIdx.z * zstride;

    const int r0 = tid >> 2, c0 = tid & 3;
    const int r1 = (tid + 256) >> 2, c1 = tid & 3;
    const long long aoff0 = (long long)(m0 + r0) * lda, aoff1 = (long long)(m0 + r1) * lda;
    const long long boff0 = (long long)(n0 + r0) * ldb, boff1 = (long long)(n0 + r1) * ldb;

#define ISSUE_CHUNK(i) do { \
    int kb = k0 + (i) * 32; \
    uint32_t st = sb + ((i) & 1) * STAGE_B; \
    CP16(st + 0*PLANE_B + r0*PITCH + c0*16, (const char*)Ah  + (aoff0 + kb + c0*8)*2); \
    CP16(st + 0*PLANE_B + r1*PITCH + c1*16, (const char*)Ah  + (aoff1 + kb + c1*8)*2); \
    CP16(st + 1*PLANE_B + r0*PITCH + c0*16, (const char*)Alo + (aoff0 + kb + c0*8)*2); \
    CP16(st + 1*PLANE_B + r1*PITCH + c1*16, (const char*)Alo + (aoff1 + kb + c1*8)*2); \
    CP16(st + 2*PLANE_B + r0*PITCH + c0*16, (const char*)Bh  + (boff0 + kb + c0*8)*2); \
    CP16(st + 2*PLANE_B + r1*PITCH + c1*16, (const char*)Bh  + (boff1 + kb + c1*8)*2); \
    CP16(st + 3*PLANE_B + r0*PITCH + c0*16, (const char*)Blo + (boff0 + kb + c0*8)*2); \
    CP16(st + 3*PLANE_B + r1*PITCH + c1*16, (const char*)Blo + (boff1 + kb + c1*8)*2); \
    } while (0)

    float acc[2][8][4];
#pragma unroll
    for (int mt = 0; mt < 2; mt++)
#pragma unroll
        for (int j = 0; j < 8; j++)
#pragma unroll
            for (int q = 0; q < 4; q++) acc[mt][j][q] = 0.f;

    const uint32_t a_lane = (uint32_t)(((lane & 7) + ((lane >> 3) & 1) * 8) * PITCH
                                       + (lane >> 4) * 16);
    const uint32_t b_lane = (uint32_t)(((lane & 7) + (lane >> 4) * 8) * PITCH
                                       + ((lane >> 3) & 1) * 16);

    ISSUE_CHUNK(0);
    CP_COMMIT();

    for (int i = 0; i < NC; i++) {
        if (i + 1 < NC) ISSUE_CHUNK(i + 1);
        CP_COMMIT();
        CP_WAIT1();
        __syncthreads();

        const uint32_t st = sb + (i & 1) * STAGE_B;
#pragma unroll
        for (int s = 0; s < 2; s++) {
            uint32_t ah[2][4], al[2][4], bh[4][4], bl[4][4];
#pragma unroll
            for (int mt = 0; mt < 2; mt++) {
                uint32_t aa = st + (uint32_t)((warp_m * 32 + mt * 16) * PITCH + s * 32) + a_lane;
                LDSM4(ah[mt], aa);
                LDSM4(al[mt], aa + PLANE_B);
            }
#pragma unroll
            for (int nt = 0; nt < 4; nt++) {
                uint32_t ba = st + 2 * PLANE_B
                            + (uint32_t)((warp_n * 64 + nt * 16) * PITCH + s * 32) + b_lane;
                LDSM4(bh[nt], ba);
                LDSM4(bl[nt], ba + PLANE_B);
            }
#pragma unroll
            for (int mt = 0; mt < 2; mt++)
#pragma unroll
                for (int j = 0; j < 8; j++) {
                    uint32_t bjh0 = bh[j >> 1][(j & 1) * 2], bjh1 = bh[j >> 1][(j & 1) * 2 + 1];
                    uint32_t bjl0 = bl[j >> 1][(j & 1) * 2], bjl1 = bl[j >> 1][(j & 1) * 2 + 1];
                    MMA(acc[mt][j], ah[mt], bjh0, bjh1);
                    MMA(acc[mt][j], ah[mt], bjl0, bjl1);
                    MMA(acc[mt][j], al[mt], bjh0, bjh1);
                }
        }
        __syncthreads();
    }

    const int mbase = m0 + warp_m * 32;
    const int nbase = n0 + warp_n * 64;
#pragma unroll
    for (int mt = 0; mt < 2; mt++)
#pragma unroll
        for (int j = 0; j < 8; j++) {
            float* d = out + (long long)(mbase + mt * 16 + (lane >> 2)) * ldo
                           + nbase + j * 8 + (lane & 3) * 2;
            d[0] = acc[mt][j][0];
            d[1] = acc[mt][j][1];
            d[(long long)ldo * 8]     = acc[mt][j][2];
            d[(long long)ldo * 8 + 1] = acc[mt][j][3];
        }
}

// -------- reduce partials + lam scale -> Al bf16 hi/lo ----------------------
__global__ void k_reduce(const float* __restrict__ lam) {
    int i = blockIdx.x * 256 + threadIdx.x;
    float4 s = make_float4(0.f, 0.f, 0.f, 0.f);
#pragma unroll
    for (int z = 0; z < SPLITS; z++) {
        float4 p = *(const float4*)(g_part + (long long)z * NB * RR + i * 4);
        s.x += p.x; s.y += p.y; s.z += p.z; s.w += p.w;
    }
    int k = (i * 4) & (RR - 1);
    s.x *= lam[k]; s.y *= lam[k + 1]; s.z *= lam[k + 2]; s.w *= lam[k + 3];
    split_store(g_Al_h, g_Al_l, i * 4 + 0, s.x);
    split_store(g_Al_h, g_Al_l, i * 4 + 1, s.y);
    split_store(g_Al_h, g_Al_l, i * 4 + 2, s.z);
    split_store(g_Al_h, g_Al_l, i * 4 + 3, s.w);
}

extern "C" void kernel_launch(void* const* d_in, const int* in_sizes, int n_in,
                              void* d_out, int out_size) {
    const float* rho = (const float*)d_in[0];
    const float* lam = (const float*)d_in[1];
    float* phi = (float*)d_out;
    (void)in_sizes; (void)n_in; (void)out_size;

    __nv_bfloat16 *pCh, *pCl, *pCTh, *pCTl, *pRh, *pRl, *pAh, *pAl;
    float* pPart;
    cudaGetSymbolAddress((void**)&pCh, g_C_h);
    cudaGetSymbolAddress((void**)&pCl, g_C_l);
    cudaGetSymbolAddress((void**)&pCTh, g_CT_h);
    cudaGetSymbolAddress((void**)&pCTl, g_CT_l);
    cudaGetSymbolAddress((void**)&pRh, g_rho_h);
    cudaGetSymbolAddress((void**)&pRl, g_rho_l);
    cudaGetSymbolAddress((void**)&pAh, g_Al_h);
    cudaGetSymbolAddress((void**)&pAl, g_Al_l);
    cudaGetSymbolAddress((void**)&pPart, g_part);
    cudaFuncSetAttribute(k_gemm, cudaFuncAttributeMaxDynamicSharedMemorySize, SMEM_SZ);

    k_lut<<<64, 256>>>();
    k_build<<<dim3(128, 8), dim3(32, 8)>>>();
    k_split_rho<<<(NB * NG) / 1024, 256>>>(rho);
    // GEMM1: part[z] = rho @ Cs^T   (M=1024, N=256, K=4096, split-K=16)
    k_gemm<<<dim3(8, 2, SPLITS), 256, SMEM_SZ>>>(pRh, pRl, pCh, pCl, pPart,
                                                 NG, NG, RR, NG / SPLITS,
                                                 (long long)NB * RR);
    k_reduce<<<(NB * RR) / 1024, 256>>>(lam);
    // GEMM2: phi = Al @ CT^T        (M=1024, N=4096, K=256)
    k_gemm<<<dim3(8, 32, 1), 256, SMEM_SZ>>>(pAh, pAl, pCTh, pCTl, phi,
                                             RR, RR, NG, RR, 0);
}

// round 5
// speedup vs baseline: 2.7953x; 1.0491x over previous
#include <cuda_runtime.h>
#include <cuda_bf16.h>
#include <cstdint>

// phi = (lam ⊙ (rho @ Cs^T)) @ Cs, rank-256. B=1024, N=4096, R=256.
// HMMA m16n8k16 bf16 hi/lo split (3 MMAs), cp.async 3-stage ring.
// R5: 128x256 CTA tile, 512 threads, one __syncthreads per K-chunk,
//     single-wave grids (128 CTAs) for both GEMMs.

#define NB 1024
#define NG 4096
#define RR 256
#define SPLITS 16

__device__ __align__(16) __nv_bfloat16 g_C_h[RR * NG];
__device__ __align__(16) __nv_bfloat16 g_C_l[RR * NG];
__device__ __align__(16) __nv_bfloat16 g_CT_h[NG * RR];
__device__ __align__(16) __nv_bfloat16 g_CT_l[NG * RR];
__device__ __align__(16) __nv_bfloat16 g_rho_h[NB * NG];
__device__ __align__(16) __nv_bfloat16 g_rho_l[NB * NG];
__device__ __align__(16) __nv_bfloat16 g_Al_h[NB * RR];
__device__ __align__(16) __nv_bfloat16 g_Al_l[NB * RR];
__device__ __align__(16) float g_part[SPLITS * NB * RR];
__device__ __align__(16) float g_lut_c[16384];
__device__ __align__(16) float g_lut_s[16384];

// ----------------------------- PTX helpers ---------------------------------
__device__ __forceinline__ uint32_t smem_u32(const void* p) {
    uint32_t a;
    asm("{ .reg .u64 t; cvta.to.shared.u64 t, %1; cvt.u32.u64 %0, t; }" : "=r"(a) : "l"(p));
    return a;
}
#define CP16(dst, src) \
    asm volatile("cp.async.cg.shared.global [%0], [%1], 16;" :: "r"(dst), "l"(src))
#define CP_COMMIT() asm volatile("cp.async.commit_group;" ::: "memory")
#define CP_WAIT1()  asm volatile("cp.async.wait_group 1;" ::: "memory")
#define LDSM4(r, a) \
    asm volatile("ldmatrix.sync.aligned.m8n8.x4.shared.b16 {%0,%1,%2,%3}, [%4];" \
        : "=r"((r)[0]), "=r"((r)[1]), "=r"((r)[2]), "=r"((r)[3]) : "r"(a))
#define MMA(c, a, b0, b1) \
    asm volatile("mma.sync.aligned.m16n8k16.row.col.f32.bf16.bf16.f32 " \
        "{%0,%1,%2,%3},{%4,%5,%6,%7},{%8,%9},{%0,%1,%2,%3};" \
        : "+f"((c)[0]), "+f"((c)[1]), "+f"((c)[2]), "+f"((c)[3]) \
        : "r"((a)[0]), "r"((a)[1]), "r"((a)[2]), "r"((a)[3]), "r"(b0), "r"(b1))

// ------------------------------- LUT + builds -------------------------------
__global__ void k_lut() {
    int j = blockIdx.x * 256 + threadIdx.x;
    float x = (float)j * (1.0f / 8192.0f);
    float sc = sqrtf(2.0f / 4096.0f);
    g_lut_c[j] = cospif(x) * sc;
    g_lut_s[j] = sinpif(x) * sc;
}

#define PI_F  3.14159274101257324f
#define PI_LO (-8.742277657347586e-8f)

__device__ __forceinline__ void dct_hi_lo(int n, int kk, __nv_bfloat16& h, __nv_bfloat16& l) {
    float t1 = 2.0f * (float)n + 1.0f;
    float t2 = PI_F * t1;
    float t3 = t2 * (float)kk;
    float th = t3 * (1.0f / 8192.0f);
    int m = (2 * n + 1) * kk;
    float x = (float)m * (1.0f / 8192.0f);
    float e = fmaf(-PI_F, x, th) - PI_LO * x;
    int j = m & 16383;
    float v = __ldg(&g_lut_c[j]) - e * __ldg(&g_lut_s[j]);
    h = __float2bfloat16(v);
    l = __float2bfloat16(v - __bfloat162float(h));
}

__global__ void k_build() {          // grid (128, 8), block (32, 8)
    __shared__ __nv_bfloat16 sh[32][33], sl[32][33];
    const int tx = threadIdx.x, ty = threadIdx.y;
    const int n0 = blockIdx.x * 32, k0 = blockIdx.y * 32;
#pragma unroll
    for (int i = 0; i < 4; i++) {
        int kl = ty + i * 8;
        __nv_bfloat16 h, l;
        dct_hi_lo(n0 + tx, k0 + kl + 1, h, l);
        g_C_h[(k0 + kl) * NG + n0 + tx] = h;
        g_C_l[(k0 + kl) * NG + n0 + tx] = l;
        sh[kl][tx] = h; sl[kl][tx] = l;
    }
    __syncthreads();
#pragma unroll
    for (int i = 0; i < 4; i++) {
        int nl = ty + i * 8;
        g_CT_h[(n0 + nl) * RR + k0 + tx] = sh[tx][nl];
        g_CT_l[(n0 + nl) * RR + k0 + tx] = sl[tx][nl];
    }
}

__device__ __forceinline__ void split_store(__nv_bfloat16* ph, __nv_bfloat16* pl,
                                            int idx, float v) {
    __nv_bfloat16 h = __float2bfloat16(v);
    ph[idx] = h;
    pl[idx] = __float2bfloat16(v - __bfloat162float(h));
}
__global__ void k_split_rho(const float* __restrict__ rho) {
    int i = blockIdx.x * 256 + threadIdx.x;
    float4 v = *(const float4*)(rho + (size_t)i * 4);
    split_store(g_rho_h, g_rho_l, i * 4 + 0, v.x);
    split_store(g_rho_h, g_rho_l, i * 4 + 1, v.y);
    split_store(g_rho_h, g_rho_l, i * 4 + 2, v.z);
    split_store(g_rho_h, g_rho_l, i * 4 + 3, v.w);
}

// --------------- HMMA GEMM: out[M,N] = A[M,K] @ B[N,K]^T --------------------
// CTA tile 128x256, 512 threads (16 warps, 4x4), warp tile 32x64.
// K-chunk 32, 3-stage cp.async ring, one __syncthreads per chunk.
// Stage: Ah[128x80] Al[128x80] Bh[256x80] Bl[256x80] = 61440 B.
#define PITCH   80
#define A_PL    (128 * PITCH)           // 10240
#define B_PL    (256 * PITCH)           // 20480
#define STAGE_B (2 * A_PL + 2 * B_PL)   // 61440
#define SMEM_SZ (3 * STAGE_B)           // 184320

__global__ void __launch_bounds__(512, 1) k_gemm(
    const __nv_bfloat16* __restrict__ Ah, const __nv_bfloat16* __restrict__ Alo,
    const __nv_bfloat16* __restrict__ Bh, const __nv_bfloat16* __restrict__ Blo,
    float* __restrict__ out, int lda, int ldb, int ldo,
    int kper, long long zstride)
{
    extern __shared__ char smem[];
    const uint32_t sb = smem_u32(smem);
    const int tid = threadIdx.x;
    const int lane = tid & 31;
    const int wid = tid >> 5;
    const int warp_m = wid & 3;
    const int warp_n = wid >> 2;
    const int m0 = blockIdx.x * 128;
    const int n0 = blockIdx.y * 256;
    const int k0 = blockIdx.z * kper;
    const int NC = kper >> 5;
    out += (long long)blockIdx.z * zstride;

    // cp.async mapping: A 512 cp16 (1/thread/plane), B 1024 (2/thread/plane)
    const int ar = tid >> 2, ac = tid & 3;
    const int br1 = (tid + 512) >> 2;
    const long long aoff  = (long long)(m0 + ar) * lda;
    const long long boff0 = (long long)(n0 + ar) * ldb;
    const long long boff1 = (long long)(n0 + br1) * ldb;

#define ISSUE(i) do { \
    int kb = k0 + (i) * 32; \
    uint32_t st = sb + (uint32_t)((i) % 3) * STAGE_B; \
    CP16(st + ar*PITCH + ac*16,                      (const char*)Ah  + (aoff  + kb + ac*8)*2); \
    CP16(st + A_PL + ar*PITCH + ac*16,               (const char*)Alo + (aoff  + kb + ac*8)*2); \
    CP16(st + 2*A_PL + ar*PITCH + ac*16,             (const char*)Bh  + (boff0 + kb + ac*8)*2); \
    CP16(st + 2*A_PL + br1*PITCH + ac*16,            (const char*)Bh  + (boff1 + kb + ac*8)*2); \
    CP16(st + 2*A_PL + B_PL + ar*PITCH + ac*16,      (const char*)Blo + (boff0 + kb + ac*8)*2); \
    CP16(st + 2*A_PL + B_PL + br1*PITCH + ac*16,     (const char*)Blo + (boff1 + kb + ac*8)*2); \
    } while (0)

    float acc[2][8][4];
#pragma unroll
    for (int mt = 0; mt < 2; mt++)
#pragma unroll
        for (int j = 0; j < 8; j++)
#pragma unroll
            for (int q = 0; q < 4; q++) acc[mt][j][q] = 0.f;

    const uint32_t a_lane = (uint32_t)(((lane & 7) + ((lane >> 3) & 1) * 8) * PITCH
                                       + (lane >> 4) * 16);
    const uint32_t b_lane = (uint32_t)(((lane & 7) + (lane >> 4) * 8) * PITCH
                                       + ((lane >> 3) & 1) * 16);

    ISSUE(0); CP_COMMIT();
    ISSUE(1); CP_COMMIT();

    for (int i = 0; i < NC; i++) {
        CP_WAIT1();
        __syncthreads();
        if (i + 2 < NC) ISSUE(i + 2);
        CP_COMMIT();                      // empty group when no issue: keeps count

        const uint32_t st = sb + (uint32_t)(i % 3) * STAGE_B;
#pragma unroll
        for (int s = 0; s < 2; s++) {
            uint32_t ah[2][4], al[2][4];
#pragma unroll
            for (int mt = 0; mt < 2; mt++) {
                uint32_t aa = st + (uint32_t)((warp_m * 32 + mt * 16) * PITCH + s * 32) + a_lane;
                LDSM4(ah[mt], aa);
                LDSM4(al[mt], aa + A_PL);
            }
#pragma unroll
            for (int nt = 0; nt < 4; nt++) {
                uint32_t bh[4], bl[4];
                uint32_t ba = st + 2 * A_PL
                            + (uint32_t)((warp_n * 64 + nt * 16) * PITCH + s * 32) + b_lane;
                LDSM4(bh, ba);
                LDSM4(bl, ba + B_PL);
#pragma unroll
                for (int mt = 0; mt < 2; mt++)
#pragma unroll
                    for (int h = 0; h < 2; h++) {
                        int j = nt * 2 + h;
                        MMA(acc[mt][j], ah[mt], bh[h * 2], bh[h * 2 + 1]);
                        MMA(acc[mt][j], ah[mt], bl[h * 2], bl[h * 2 + 1]);
                        MMA(acc[mt][j], al[mt], bh[h * 2], bh[h * 2 + 1]);
                    }
            }
        }
    }

    const int mbase = m0 + warp_m * 32;
    const int nbase = n0 + warp_n * 64;
#pragma unroll
    for (int mt = 0; mt < 2; mt++)
#pragma unroll
        for (int j = 0; j < 8; j++) {
            float* d = out + (long long)(mbase + mt * 16 + (lane >> 2)) * ldo
                           + nbase + j * 8 + (lane & 3) * 2;
            d[0] = acc[mt][j][0];
            d[1] = acc[mt][j][1];
            d[(long long)ldo * 8]     = acc[mt][j][2];
            d[(long long)ldo * 8 + 1] = acc[mt][j][3];
        }
}

// -------- reduce partials + lam scale -> Al bf16 hi/lo ----------------------
__global__ void k_reduce(const float* __restrict__ lam) {
    int i = blockIdx.x * 256 + threadIdx.x;
    float4 s = make_float4(0.f, 0.f, 0.f, 0.f);
#pragma unroll
    for (int z = 0; z < SPLITS; z++) {
        float4 p = *(const float4*)(g_part + (long long)z * NB * RR + i * 4);
        s.x += p.x; s.y += p.y; s.z += p.z; s.w += p.w;
    }
    int k = (i * 4) & (RR - 1);
    s.x *= lam[k]; s.y *= lam[k + 1]; s.z *= lam[k + 2]; s.w *= lam[k + 3];
    split_store(g_Al_h, g_Al_l, i * 4 + 0, s.x);
    split_store(g_Al_h, g_Al_l, i * 4 + 1, s.y);
    split_store(g_Al_h, g_Al_l, i * 4 + 2, s.z);
    split_store(g_Al_h, g_Al_l, i * 4 + 3, s.w);
}

extern "C" void kernel_launch(void* const* d_in, const int* in_sizes, int n_in,
                              void* d_out, int out_size) {
    const float* rho = (const float*)d_in[0];
    const float* lam = (const float*)d_in[1];
    float* phi = (float*)d_out;
    (void)in_sizes; (void)n_in; (void)out_size;

    __nv_bfloat16 *pCh, *pCl, *pCTh, *pCTl, *pRh, *pRl, *pAh, *pAl;
    float* pPart;
    cudaGetSymbolAddress((void**)&pCh, g_C_h);
    cudaGetSymbolAddress((void**)&pCl, g_C_l);
    cudaGetSymbolAddress((void**)&pCTh, g_CT_h);
    cudaGetSymbolAddress((void**)&pCTl, g_CT_l);
    cudaGetSymbolAddress((void**)&pRh, g_rho_h);
    cudaGetSymbolAddress((void**)&pRl, g_rho_l);
    cudaGetSymbolAddress((void**)&pAh, g_Al_h);
    cudaGetSymbolAddress((void**)&pAl, g_Al_l);
    cudaGetSymbolAddress((void**)&pPart, g_part);
    cudaFuncSetAttribute(k_gemm, cudaFuncAttributeMaxDynamicSharedMemorySize, SMEM_SZ);

    k_lut<<<64, 256>>>();
    k_build<<<dim3(128, 8), dim3(32, 8)>>>();
    k_split_rho<<<(NB * NG) / 1024, 256>>>(rho);
    // GEMM1: part[z] = rho @ Cs^T  (M=1024, N=256, K=4096, split-K=16 -> 128 CTAs)
    k_gemm<<<dim3(8, 1, SPLITS), 512, SMEM_SZ>>>(pRh, pRl, pCh, pCl, pPart,
                                                 NG, NG, RR, NG / SPLITS,
                                                 (long long)NB * RR);
    k_reduce<<<(NB * RR) / 1024, 256>>>(lam);
    // GEMM2: phi = Al @ CT^T       (M=1024, N=4096, K=256 -> 128 CTAs)
    k_gemm<<<dim3(8, 16, 1), 512, SMEM_SZ>>>(pAh, pAl, pCTh, pCTl, phi,
                                             RR, RR, NG, RR, 0);
}

// round 6
// speedup vs baseline: 2.8042x; 1.0032x over previous
#include <cuda_runtime.h>
#include <cuda_bf16.h>
#include <cstdint>

// phi = (lam ⊙ (rho @ Cs^T)) @ Cs, rank-256. B=1024, N=4096, R=256.
// HMMA m16n8k16 bf16 hi/lo split (3 MMAs), cp.async 3-stage ring.
// R6: split-pass reorder — consecutive MMAs target different accumulators
//     (RAW chain distance 1 -> 4) to kill HMMA latency stalls.

#define NB 1024
#define NG 4096
#define RR 256
#define SPLITS 16

__device__ __align__(16) __nv_bfloat16 g_C_h[RR * NG];
__device__ __align__(16) __nv_bfloat16 g_C_l[RR * NG];
__device__ __align__(16) __nv_bfloat16 g_CT_h[NG * RR];
__device__ __align__(16) __nv_bfloat16 g_CT_l[NG * RR];
__device__ __align__(16) __nv_bfloat16 g_rho_h[NB * NG];
__device__ __align__(16) __nv_bfloat16 g_rho_l[NB * NG];
__device__ __align__(16) __nv_bfloat16 g_Al_h[NB * RR];
__device__ __align__(16) __nv_bfloat16 g_Al_l[NB * RR];
__device__ __align__(16) float g_part[SPLITS * NB * RR];
__device__ __align__(16) float g_lut_c[16384];
__device__ __align__(16) float g_lut_s[16384];

// ----------------------------- PTX helpers ---------------------------------
__device__ __forceinline__ uint32_t smem_u32(const void* p) {
    uint32_t a;
    asm("{ .reg .u64 t; cvta.to.shared.u64 t, %1; cvt.u32.u64 %0, t; }" : "=r"(a) : "l"(p));
    return a;
}
#define CP16(dst, src) \
    asm volatile("cp.async.cg.shared.global [%0], [%1], 16;" :: "r"(dst), "l"(src))
#define CP_COMMIT() asm volatile("cp.async.commit_group;" ::: "memory")
#define CP_WAIT1()  asm volatile("cp.async.wait_group 1;" ::: "memory")
#define LDSM4(r, a) \
    asm volatile("ldmatrix.sync.aligned.m8n8.x4.shared.b16 {%0,%1,%2,%3}, [%4];" \
        : "=r"((r)[0]), "=r"((r)[1]), "=r"((r)[2]), "=r"((r)[3]) : "r"(a))
#define MMA(c, a, b0, b1) \
    asm volatile("mma.sync.aligned.m16n8k16.row.col.f32.bf16.bf16.f32 " \
        "{%0,%1,%2,%3},{%4,%5,%6,%7},{%8,%9},{%0,%1,%2,%3};" \
        : "+f"((c)[0]), "+f"((c)[1]), "+f"((c)[2]), "+f"((c)[3]) \
        : "r"((a)[0]), "r"((a)[1]), "r"((a)[2]), "r"((a)[3]), "r"(b0), "r"(b1))

// ------------------------------- LUT + builds -------------------------------
__global__ void k_lut() {
    int j = blockIdx.x * 256 + threadIdx.x;
    float x = (float)j * (1.0f / 8192.0f);
    float sc = sqrtf(2.0f / 4096.0f);
    g_lut_c[j] = cospif(x) * sc;
    g_lut_s[j] = sinpif(x) * sc;
}

#define PI_F  3.14159274101257324f
#define PI_LO (-8.742277657347586e-8f)

__device__ __forceinline__ void dct_hi_lo(int n, int kk, __nv_bfloat16& h, __nv_bfloat16& l) {
    float t1 = 2.0f * (float)n + 1.0f;
    float t2 = PI_F * t1;
    float t3 = t2 * (float)kk;
    float th = t3 * (1.0f / 8192.0f);
    int m = (2 * n + 1) * kk;
    float x = (float)m * (1.0f / 8192.0f);
    float e = fmaf(-PI_F, x, th) - PI_LO * x;
    int j = m & 16383;
    float v = __ldg(&g_lut_c[j]) - e * __ldg(&g_lut_s[j]);
    h = __float2bfloat16(v);
    l = __float2bfloat16(v - __bfloat162float(h));
}

__global__ void k_build() {          // grid (128, 8), block (32, 8)
    __shared__ __nv_bfloat16 sh[32][33], sl[32][33];
    const int tx = threadIdx.x, ty = threadIdx.y;
    const int n0 = blockIdx.x * 32, k0 = blockIdx.y * 32;
#pragma unroll
    for (int i = 0; i < 4; i++) {
        int kl = ty + i * 8;
        __nv_bfloat16 h, l;
        dct_hi_lo(n0 + tx, k0 + kl + 1, h, l);
        g_C_h[(k0 + kl) * NG + n0 + tx] = h;
        g_C_l[(k0 + kl) * NG + n0 + tx] = l;
        sh[kl][tx] = h; sl[kl][tx] = l;
    }
    __syncthreads();
#pragma unroll
    for (int i = 0; i < 4; i++) {
        int nl = ty + i * 8;
        g_CT_h[(n0 + nl) * RR + k0 + tx] = sh[tx][nl];
        g_CT_l[(n0 + nl) * RR + k0 + tx] = sl[tx][nl];
    }
}

__device__ __forceinline__ void split_store(__nv_bfloat16* ph, __nv_bfloat16* pl,
                                            int idx, float v) {
    __nv_bfloat16 h = __float2bfloat16(v);
    ph[idx] = h;
    pl[idx] = __float2bfloat16(v - __bfloat162float(h));
}
__global__ void k_split_rho(const float* __restrict__ rho) {
    int i = blockIdx.x * 256 + threadIdx.x;
    float4 v = *(const float4*)(rho + (size_t)i * 4);
    split_store(g_rho_h, g_rho_l, i * 4 + 0, v.x);
    split_store(g_rho_h, g_rho_l, i * 4 + 1, v.y);
    split_store(g_rho_h, g_rho_l, i * 4 + 2, v.z);
    split_store(g_rho_h, g_rho_l, i * 4 + 3, v.w);
}

// --------------- HMMA GEMM: out[M,N] = A[M,K] @ B[N,K]^T --------------------
// CTA tile 128x256, 512 threads (16 warps, 4x4), warp tile 32x64.
// K-chunk 32, 3-stage cp.async ring, one __syncthreads per chunk.
#define PITCH   80
#define A_PL    (128 * PITCH)
#define B_PL    (256 * PITCH)
#define STAGE_B (2 * A_PL + 2 * B_PL)   // 61440
#define SMEM_SZ (3 * STAGE_B)           // 184320

__global__ void __launch_bounds__(512, 1) k_gemm(
    const __nv_bfloat16* __restrict__ Ah, const __nv_bfloat16* __restrict__ Alo,
    const __nv_bfloat16* __restrict__ Bh, const __nv_bfloat16* __restrict__ Blo,
    float* __restrict__ out, int lda, int ldb, int ldo,
    int kper, long long zstride)
{
    extern __shared__ char smem[];
    const uint32_t sb = smem_u32(smem);
    const int tid = threadIdx.x;
    const int lane = tid & 31;
    const int wid = tid >> 5;
    const int warp_m = wid & 3;
    const int warp_n = wid >> 2;
    const int m0 = blockIdx.x * 128;
    const int n0 = blockIdx.y * 256;
    const int k0 = blockIdx.z * kper;
    const int NC = kper >> 5;
    out += (long long)blockIdx.z * zstride;

    const int ar = tid >> 2, ac = tid & 3;
    const int br1 = (tid + 512) >> 2;
    const long long aoff  = (long long)(m0 + ar) * lda;
    const long long boff0 = (long long)(n0 + ar) * ldb;
    const long long boff1 = (long long)(n0 + br1) * ldb;

#define ISSUE(i) do { \
    int kb = k0 + (i) * 32; \
    uint32_t st = sb + (uint32_t)((i) % 3) * STAGE_B; \
    CP16(st + ar*PITCH + ac*16,                      (const char*)Ah  + (aoff  + kb + ac*8)*2); \
    CP16(st + A_PL + ar*PITCH + ac*16,               (const char*)Alo + (aoff  + kb + ac*8)*2); \
    CP16(st + 2*A_PL + ar*PITCH + ac*16,             (const char*)Bh  + (boff0 + kb + ac*8)*2); \
    CP16(st + 2*A_PL + br1*PITCH + ac*16,            (const char*)Bh  + (boff1 + kb + ac*8)*2); \
    CP16(st + 2*A_PL + B_PL + ar*PITCH + ac*16,      (const char*)Blo + (boff0 + kb + ac*8)*2); \
    CP16(st + 2*A_PL + B_PL + br1*PITCH + ac*16,     (const char*)Blo + (boff1 + kb + ac*8)*2); \
    } while (0)

    float acc[2][8][4];
#pragma unroll
    for (int mt = 0; mt < 2; mt++)
#pragma unroll
        for (int j = 0; j < 8; j++)
#pragma unroll
            for (int q = 0; q < 4; q++) acc[mt][j][q] = 0.f;

    const uint32_t a_lane = (uint32_t)(((lane & 7) + ((lane >> 3) & 1) * 8) * PITCH
                                       + (lane >> 4) * 16);
    const uint32_t b_lane = (uint32_t)(((lane & 7) + (lane >> 4) * 8) * PITCH
                                       + ((lane >> 3) & 1) * 16);

    ISSUE(0); CP_COMMIT();
    ISSUE(1); CP_COMMIT();

    for (int i = 0; i < NC; i++) {
        CP_WAIT1();
        __syncthreads();
        if (i + 2 < NC) ISSUE(i + 2);
        CP_COMMIT();

        const uint32_t st = sb + (uint32_t)(i % 3) * STAGE_B;
#pragma unroll
        for (int s = 0; s < 2; s++) {
            uint32_t ah[2][4], al[2][4];
#pragma unroll
            for (int mt = 0; mt < 2; mt++) {
                uint32_t aa = st + (uint32_t)((warp_m * 32 + mt * 16) * PITCH + s * 32) + a_lane;
                LDSM4(ah[mt], aa);
                LDSM4(al[mt], aa + A_PL);
            }
#pragma unroll
            for (int nt = 0; nt < 4; nt++) {
                uint32_t bh[4], bl[4];
                uint32_t ba = st + 2 * A_PL
                            + (uint32_t)((warp_n * 64 + nt * 16) * PITCH + s * 32) + b_lane;
                LDSM4(bh, ba);
                LDSM4(bl, ba + B_PL);
                // Pass-ordered: same-accumulator MMAs are 4 issues apart.
#pragma unroll
                for (int mt = 0; mt < 2; mt++)
#pragma unroll
                    for (int h = 0; h < 2; h++)
                        MMA(acc[mt][nt * 2 + h], ah[mt], bh[h * 2], bh[h * 2 + 1]);
#pragma unroll
                for (int mt = 0; mt < 2; mt++)
#pragma unroll
                    for (int h = 0; h < 2; h++)
                        MMA(acc[mt][nt * 2 + h], ah[mt], bl[h * 2], bl[h * 2 + 1]);
#pragma unroll
                for (int mt = 0; mt < 2; mt++)
#pragma unroll
                    for (int h = 0; h < 2; h++)
                        MMA(acc[mt][nt * 2 + h], al[mt], bh[h * 2], bh[h * 2 + 1]);
            }
        }
    }

    const int mbase = m0 + warp_m * 32;
    const int nbase = n0 + warp_n * 64;
#pragma unroll
    for (int mt = 0; mt < 2; mt++)
#pragma unroll
        for (int j = 0; j < 8; j++) {
            float* d = out + (long long)(mbase + mt * 16 + (lane >> 2)) * ldo
                           + nbase + j * 8 + (lane & 3) * 2;
            d[0] = acc[mt][j][0];
            d[1] = acc[mt][j][1];
            d[(long long)ldo * 8]     = acc[mt][j][2];
            d[(long long)ldo * 8 + 1] = acc[mt][j][3];
        }
}

// -------- reduce partials + lam scale -> Al bf16 hi/lo ----------------------
__global__ void k_reduce(const float* __restrict__ lam) {
    int i = blockIdx.x * 256 + threadIdx.x;
    float4 s = make_float4(0.f, 0.f, 0.f, 0.f);
#pragma unroll
    for (int z = 0; z < SPLITS; z++) {
        float4 p = *(const float4*)(g_part + (long long)z * NB * RR + i * 4);
        s.x += p.x; s.y += p.y; s.z += p.z; s.w += p.w;
    }
    int k = (i * 4) & (RR - 1);
    s.x *= lam[k]; s.y *= lam[k + 1]; s.z *= lam[k + 2]; s.w *= lam[k + 3];
    split_store(g_Al_h, g_Al_l, i * 4 + 0, s.x);
    split_store(g_Al_h, g_Al_l, i * 4 + 1, s.y);
    split_store(g_Al_h, g_Al_l, i * 4 + 2, s.z);
    split_store(g_Al_h, g_Al_l, i * 4 + 3, s.w);
}

extern "C" void kernel_launch(void* const* d_in, const int* in_sizes, int n_in,
                              void* d_out, int out_size) {
    const float* rho = (const float*)d_in[0];
    const float* lam = (const float*)d_in[1];
    float* phi = (float*)d_out;
    (void)in_sizes; (void)n_in; (void)out_size;

    __nv_bfloat16 *pCh, *pCl, *pCTh, *pCTl, *pRh, *pRl, *pAh, *pAl;
    float* pPart;
    cudaGetSymbolAddress((void**)&pCh, g_C_h);
    cudaGetSymbolAddress((void**)&pCl, g_C_l);
    cudaGetSymbolAddress((void**)&pCTh, g_CT_h);
    cudaGetSymbolAddress((void**)&pCTl, g_CT_l);
    cudaGetSymbolAddress((void**)&pRh, g_rho_h);
    cudaGetSymbolAddress((void**)&pRl, g_rho_l);
    cudaGetSymbolAddress((void**)&pAh, g_Al_h);
    cudaGetSymbolAddress((void**)&pAl, g_Al_l);
    cudaGetSymbolAddress((void**)&pPart, g_part);
    cudaFuncSetAttribute(k_gemm, cudaFuncAttributeMaxDynamicSharedMemorySize, SMEM_SZ);

    k_lut<<<64, 256>>>();
    k_build<<<dim3(128, 8), dim3(32, 8)>>>();
    k_split_rho<<<(NB * NG) / 1024, 256>>>(rho);
    // GEMM1: part[z] = rho @ Cs^T  (M=1024, N=256, K=4096, split-K=16 -> 128 CTAs)
    k_gemm<<<dim3(8, 1, SPLITS), 512, SMEM_SZ>>>(pRh, pRl, pCh, pCl, pPart,
                                                 NG, NG, RR, NG / SPLITS,
                                                 (long long)NB * RR);
    k_reduce<<<(NB * RR) / 1024, 256>>>(lam);
    // GEMM2: phi = Al @ CT^T       (M=1024, N=4096, K=256 -> 128 CTAs)
    k_gemm<<<dim3(8, 16, 1), 512, SMEM_SZ>>>(pAh, pAl, pCTh, pCTl, phi,
                                             RR, RR, NG, RR, 0);
}

// round 7
// speedup vs baseline: 3.9588x; 1.4117x over previous
#include <cuda_runtime.h>
#include <cuda_fp16.h>
#include <cstdint>

// phi = (lam ⊙ (rho @ Cs^T)) @ Cs, rank-256. B=1024, N=4096, R=256.
// R7: single-pass fp16 HMMA m16n8k16 (fp32 accum). fp16/tf32 have identical
// 10-bit mantissas but fp16 does 2x MACs/instr; predicted rel_err ~3e-4.
// 3x fewer MMA instructions than the bf16 hi/lo 3-pass of R6.

#define NB 1024
#define NG 4096
#define RR 256
#define SPLITS 16

__device__ __align__(16) __half g_C_h[RR * NG];
__device__ __align__(16) __half g_CT_h[NG * RR];
__device__ __align__(16) __half g_rho_h[NB * NG];
__device__ __align__(16) __half g_Al_h[NB * RR];
__device__ __align__(16) float g_part[SPLITS * NB * RR];
__device__ __align__(16) float g_lut_c[16384];
__device__ __align__(16) float g_lut_s[16384];

// ----------------------------- PTX helpers ---------------------------------
__device__ __forceinline__ uint32_t smem_u32(const void* p) {
    uint32_t a;
    asm("{ .reg .u64 t; cvta.to.shared.u64 t, %1; cvt.u32.u64 %0, t; }" : "=r"(a) : "l"(p));
    return a;
}
#define CP16(dst, src) \
    asm volatile("cp.async.cg.shared.global [%0], [%1], 16;" :: "r"(dst), "l"(src))
#define CP_COMMIT() asm volatile("cp.async.commit_group;" ::: "memory")
#define CP_WAIT1()  asm volatile("cp.async.wait_group 1;" ::: "memory")
#define LDSM4(r, a) \
    asm volatile("ldmatrix.sync.aligned.m8n8.x4.shared.b16 {%0,%1,%2,%3}, [%4];" \
        : "=r"((r)[0]), "=r"((r)[1]), "=r"((r)[2]), "=r"((r)[3]) : "r"(a))
#define MMA(c, a, b0, b1) \
    asm volatile("mma.sync.aligned.m16n8k16.row.col.f32.f16.f16.f32 " \
        "{%0,%1,%2,%3},{%4,%5,%6,%7},{%8,%9},{%0,%1,%2,%3};" \
        : "+f"((c)[0]), "+f"((c)[1]), "+f"((c)[2]), "+f"((c)[3]) \
        : "r"((a)[0]), "r"((a)[1]), "r"((a)[2]), "r"((a)[3]), "r"(b0), "r"(b1))

// ------------------------------- LUT + builds -------------------------------
__global__ void k_lut() {
    int j = blockIdx.x * 256 + threadIdx.x;
    float x = (float)j * (1.0f / 8192.0f);
    float sc = sqrtf(2.0f / 4096.0f);
    g_lut_c[j] = cospif(x) * sc;
    g_lut_s[j] = sinpif(x) * sc;
}

#define PI_F  3.14159274101257324f
#define PI_LO (-8.742277657347586e-8f)

// Replicates the reference's exact fp32 rounding of theta, then evaluates
// cos(theta_f32) accurately via the LUT + first-order correction.
__device__ __forceinline__ float dct_val(int n, int kk) {
    float t1 = 2.0f * (float)n + 1.0f;
    float t2 = PI_F * t1;
    float t3 = t2 * (float)kk;
    float th = t3 * (1.0f / 8192.0f);
    int m = (2 * n + 1) * kk;
    float x = (float)m * (1.0f / 8192.0f);
    float e = fmaf(-PI_F, x, th) - PI_LO * x;
    int j = m & 16383;
    return __ldg(&g_lut_c[j]) - e * __ldg(&g_lut_s[j]);
}

__global__ void k_build() {          // grid (128, 8), block (32, 8)
    __shared__ __half sh[32][33];
    const int tx = threadIdx.x, ty = threadIdx.y;
    const int n0 = blockIdx.x * 32, k0 = blockIdx.y * 32;
#pragma unroll
    for (int i = 0; i < 4; i++) {
        int kl = ty + i * 8;
        __half h = __float2half(dct_val(n0 + tx, k0 + kl + 1));
        g_C_h[(k0 + kl) * NG + n0 + tx] = h;
        sh[kl][tx] = h;
    }
    __syncthreads();
#pragma unroll
    for (int i = 0; i < 4; i++) {
        int nl = ty + i * 8;
        g_CT_h[(n0 + nl) * RR + k0 + tx] = sh[tx][nl];
    }
}

__global__ void k_rho_h(const float* __restrict__ rho) {
    int i = blockIdx.x * 256 + threadIdx.x;          // float4 index
    float4 v = *(const float4*)(rho + (size_t)i * 4);
    __half2 p0 = __floats2half2_rn(v.x, v.y);
    __half2 p1 = __floats2half2_rn(v.z, v.w);
    uint2 u;
    u.x = *(const uint32_t*)&p0;
    u.y = *(const uint32_t*)&p1;
    *(uint2*)(g_rho_h + (size_t)i * 4) = u;
}

// --------------- HMMA GEMM: out[M,N] = A[M,K] @ B[N,K]^T --------------------
// CTA tile 128x256, 512 threads (16 warps, 4x4), warp tile 32x64.
// K-chunk 32, 3-stage cp.async ring, one __syncthreads per chunk.
#define PITCH   80
#define A_PL    (128 * PITCH)           // 10240
#define B_PL    (256 * PITCH)           // 20480
#define STAGE_B (A_PL + B_PL)           // 30720
#define SMEM_SZ (3 * STAGE_B)           // 92160

__global__ void __launch_bounds__(512, 1) k_gemm(
    const __half* __restrict__ A, const __half* __restrict__ B,
    float* __restrict__ out, int lda, int ldb, int ldo,
    int kper, long long zstride)
{
    extern __shared__ char smem[];
    const uint32_t sb = smem_u32(smem);
    const int tid = threadIdx.x;
    const int lane = tid & 31;
    const int wid = tid >> 5;
    const int warp_m = wid & 3;
    const int warp_n = wid >> 2;
    const int m0 = blockIdx.x * 128;
    const int n0 = blockIdx.y * 256;
    const int k0 = blockIdx.z * kper;
    const int NC = kper >> 5;
    out += (long long)blockIdx.z * zstride;

    const int ar = tid >> 2, ac = tid & 3;
    const int br1 = (tid + 512) >> 2;
    const long long aoff  = (long long)(m0 + ar) * lda;
    const long long boff0 = (long long)(n0 + ar) * ldb;
    const long long boff1 = (long long)(n0 + br1) * ldb;

#define ISSUE(i) do { \
    int kb = k0 + (i) * 32; \
    uint32_t st = sb + (uint32_t)((i) % 3) * STAGE_B; \
    CP16(st + ar*PITCH + ac*16,          (const char*)A + (aoff  + kb + ac*8)*2); \
    CP16(st + A_PL + ar*PITCH + ac*16,   (const char*)B + (boff0 + kb + ac*8)*2); \
    CP16(st + A_PL + br1*PITCH + ac*16,  (const char*)B + (boff1 + kb + ac*8)*2); \
    } while (0)

    float acc[2][8][4];
#pragma unroll
    for (int mt = 0; mt < 2; mt++)
#pragma unroll
        for (int j = 0; j < 8; j++)
#pragma unroll
            for (int q = 0; q < 4; q++) acc[mt][j][q] = 0.f;

    const uint32_t a_lane = (uint32_t)(((lane & 7) + ((lane >> 3) & 1) * 8) * PITCH
                                       + (lane >> 4) * 16);
    const uint32_t b_lane = (uint32_t)(((lane & 7) + (lane >> 4) * 8) * PITCH
                                       + ((lane >> 3) & 1) * 16);

    ISSUE(0); CP_COMMIT();
    ISSUE(1); CP_COMMIT();

    for (int i = 0; i < NC; i++) {
        CP_WAIT1();
        __syncthreads();
        if (i + 2 < NC) ISSUE(i + 2);
        CP_COMMIT();

        const uint32_t st = sb + (uint32_t)(i % 3) * STAGE_B;
#pragma unroll
        for (int s = 0; s < 2; s++) {
            uint32_t ah[2][4];
#pragma unroll
            for (int mt = 0; mt < 2; mt++) {
                uint32_t aa = st + (uint32_t)((warp_m * 32 + mt * 16) * PITCH + s * 32) + a_lane;
                LDSM4(ah[mt], aa);
            }
#pragma unroll
            for (int nt = 0; nt < 4; nt++) {
                uint32_t bh[4];
                uint32_t ba = st + A_PL
                            + (uint32_t)((warp_n * 64 + nt * 16) * PITCH + s * 32) + b_lane;
                LDSM4(bh, ba);
#pragma unroll
                for (int mt = 0; mt < 2; mt++)
#pragma unroll
                    for (int h = 0; h < 2; h++)
                        MMA(acc[mt][nt * 2 + h], ah[mt], bh[h * 2], bh[h * 2 + 1]);
            }
        }
    }

    const int mbase = m0 + warp_m * 32;
    const int nbase = n0 + warp_n * 64;
#pragma unroll
    for (int mt = 0; mt < 2; mt++)
#pragma unroll
        for (int j = 0; j < 8; j++) {
            float* d = out + (long long)(mbase + mt * 16 + (lane >> 2)) * ldo
                           + nbase + j * 8 + (lane & 3) * 2;
            d[0] = acc[mt][j][0];
            d[1] = acc[mt][j][1];
            d[(long long)ldo * 8]     = acc[mt][j][2];
            d[(long long)ldo * 8 + 1] = acc[mt][j][3];
        }
}

// -------- reduce partials + lam scale -> Al fp16 ----------------------------
__global__ void k_reduce(const float* __restrict__ lam) {
    int i = blockIdx.x * 256 + threadIdx.x;          // float4 index over NB*RR/4
    float4 s = make_float4(0.f, 0.f, 0.f, 0.f);
#pragma unroll
    for (int z = 0; z < SPLITS; z++) {
        float4 p = *(const float4*)(g_part + (long long)z * NB * RR + i * 4);
        s.x += p.x; s.y += p.y; s.z += p.z; s.w += p.w;
    }
    int k = (i * 4) & (RR - 1);
    s.x *= lam[k]; s.y *= lam[k + 1]; s.z *= lam[k + 2]; s.w *= lam[k + 3];
    __half2 q0 = __floats2half2_rn(s.x, s.y);
    __half2 q1 = __floats2half2_rn(s.z, s.w);
    uint2 u;
    u.x = *(const uint32_t*)&q0;
    u.y = *(const uint32_t*)&q1;
    *(uint2*)(g_Al_h + (size_t)i * 4) = u;
}

extern "C" void kernel_launch(void* const* d_in, const int* in_sizes, int n_in,
                              void* d_out, int out_size) {
    const float* rho = (const float*)d_in[0];
    const float* lam = (const float*)d_in[1];
    float* phi = (float*)d_out;
    (void)in_sizes; (void)n_in; (void)out_size;

    __half *pCh, *pCTh, *pRh, *pAh;
    float* pPart;
    cudaGetSymbolAddress((void**)&pCh, g_C_h);
    cudaGetSymbolAddress((void**)&pCTh, g_CT_h);
    cudaGetSymbolAddress((void**)&pRh, g_rho_h);
    cudaGetSymbolAddress((void**)&pAh, g_Al_h);
    cudaGetSymbolAddress((void**)&pPart, g_part);
    cudaFuncSetAttribute(k_gemm, cudaFuncAttributeMaxDynamicSharedMemorySize, SMEM_SZ);

    k_lut<<<64, 256>>>();
    k_build<<<dim3(128, 8), dim3(32, 8)>>>();
    k_rho_h<<<(NB * NG) / 1024, 256>>>(rho);
    // GEMM1: part[z] = rho @ Cs^T  (M=1024, N=256, K=4096, split-K=16 -> 128 CTAs)
    k_gemm<<<dim3(8, 1, SPLITS), 512, SMEM_SZ>>>(pRh, pCh, pPart,
                                                 NG, NG, RR, NG / SPLITS,
                                                 (long long)NB * RR);
    k_reduce<<<(NB * RR) / 1024, 256>>>(lam);
    // GEMM2: phi = Al @ CT^T       (M=1024, N=4096, K=256 -> 128 CTAs)
    k_gemm<<<dim3(8, 16, 1), 512, SMEM_SZ>>>(pAh, pCTh, phi,
                                             RR, RR, NG, RR, 0);
}

// round 9
// speedup vs baseline: 4.4912x; 1.1345x over previous
#include <cuda_runtime.h>
#include <cuda_fp16.h>
#include <cstdint>

// phi = (lam ⊙ (rho @ Cs^T)) @ Cs, rank-256. B=1024, N=4096, R=256.
// R8: kill the LDGSTS issue bottleneck (8 cyc/op was the real wall R5-R7).
// Operands are pre-tiled + pre-swizzled in global memory at build time;
// the GEMM mainloop loads each K-chunk with TWO cp.async.bulk ops (mbarrier
// completion) instead of 1536 LDGSTS. fp16 HMMA m16n8k16, fp32 accum.
//
// Tiled layouts (SW128-swizzled inside each tile):
//   A tiles: 128 rows x 64 k (fp16) = 16 KB   [m_tile][k_chunk]
//   B tiles: 256 rows x 64 k (fp16) = 32 KB   [n_tile][k_chunk]

#define NB 1024
#define NG 4096
#define RR 256
#define SPLITS 16
#define TA_EL 8192      // halfs per A tile
#define TB_EL 16384     // halfs per B tile

__device__ __align__(16) __half g_A1[NB * NG];     // rho tiled   [8][64]
__device__ __align__(16) __half g_B1[RR * NG];     // Cs tiled    [1][64]
__device__ __align__(16) __half g_B2[NG * RR];     // Cs^T tiled  [16][4]
__device__ __align__(16) __half g_A2[NB * RR];     // Al tiled    [8][4]
__device__ __align__(16) float g_part[SPLITS * NB * RR];
__device__ __align__(16) float g_lut_c[16384];
__device__ __align__(16) float g_lut_s[16384];

// ----------------------------- PTX helpers ---------------------------------
__device__ __forceinline__ uint32_t smem_u32(const void* p) {
    uint32_t a;
    asm("{ .reg .u64 t; cvta.to.shared.u64 t, %1; cvt.u32.u64 %0, t; }" : "=r"(a) : "l"(p));
    return a;
}
#define MBARRIER_INIT(addr, cnt) \
    asm volatile("mbarrier.init.shared.b64 [%0], %1;" :: "r"((uint32_t)(addr)), "r"((uint32_t)(cnt)) : "memory")
#define MBARRIER_EXPECT_TX(addr, bytes) \
    asm volatile("mbarrier.arrive.expect_tx.shared.b64 _, [%0], %1;" \
        :: "r"((uint32_t)(addr)), "r"((uint32_t)(bytes)) : "memory")
#define MBARRIER_WAIT_PARITY(addr, par) do { \
    uint32_t _mb = (uint32_t)(addr), _pa = (uint32_t)(par), _dn; \
    asm volatile("{\n\t.reg .pred p;\n\t" \
        "mbarrier.try_wait.parity.acquire.cta.shared::cta.b64 p, [%1], %2;\n\t" \
        "selp.b32 %0, 1, 0, p;\n\t}" : "=r"(_dn) : "r"(_mb), "r"(_pa) : "memory"); \
    if (!_dn) { \
        asm volatile("{\n\t.reg .pred P1;\n\tWL_%=:\n\t" \
            "mbarrier.try_wait.parity.acquire.cta.shared::cta.b64 P1, [%0], %1, 0x989680;\n\t" \
            "@P1 bra.uni WD_%=;\n\tbra.uni WL_%=;\n\tWD_%=:\n\t}" \
            :: "r"(_mb), "r"(_pa) : "memory"); \
    } } while (0)
#define BULK_G2S(dst, src, bytes, mbar) \
    asm volatile("cp.async.bulk.shared::cluster.global.mbarrier::complete_tx::bytes " \
                 "[%0], [%1], %2, [%3];" \
        :: "r"((uint32_t)(dst)), "l"(src), "r"((uint32_t)(bytes)), "r"((uint32_t)(mbar)) : "memory")
#define LDSM4(r, a) \
    asm volatile("ldmatrix.sync.aligned.m8n8.x4.shared.b16 {%0,%1,%2,%3}, [%4];" \
        : "=r"((r)[0]), "=r"((r)[1]), "=r"((r)[2]), "=r"((r)[3]) : "r"(a))
#define MMA(c, a, b0, b1) \
    asm volatile("mma.sync.aligned.m16n8k16.row.col.f32.f16.f16.f32 " \
        "{%0,%1,%2,%3},{%4,%5,%6,%7},{%8,%9},{%0,%1,%2,%3};" \
        : "+f"((c)[0]), "+f"((c)[1]), "+f"((c)[2]), "+f"((c)[3]) \
        : "r"((a)[0]), "r"((a)[1]), "r"((a)[2]), "r"((a)[3]), "r"(b0), "r"(b1))

// Tile-internal offset (in halfs) for (row, kcol): 64 halfs/row = 128 B,
// 16B-unit u = kcol>>3 swizzled by row&7. Valid for both 128- and 256-row tiles.
__device__ __forceinline__ int tile_off(int r, int kcol) {
    int u = kcol >> 3;
    return r * 64 + ((u ^ (r & 7)) << 3) + (kcol & 7);
}

// ------------------------------- LUT + builds -------------------------------
__global__ void k_lut() {
    int j = blockIdx.x * 256 + threadIdx.x;
    float x = (float)j * (1.0f / 8192.0f);
    float sc = sqrtf(2.0f / 4096.0f);
    g_lut_c[j] = cospif(x) * sc;
    g_lut_s[j] = sinpif(x) * sc;
}

#define PI_F  3.14159274101257324f
#define PI_LO (-8.742277657347586e-8f)

// Replicates the reference's exact fp32 rounding of theta; accurate cos via LUT.
__device__ __forceinline__ float dct_val(int n, int kk) {
    float t1 = 2.0f * (float)n + 1.0f;
    float t2 = PI_F * t1;
    float t3 = t2 * (float)kk;
    float th = t3 * (1.0f / 8192.0f);
    int m = (2 * n + 1) * kk;
    float x = (float)m * (1.0f / 8192.0f);
    float e = fmaf(-PI_F, x, th) - PI_LO * x;
    int j = m & 16383;
    return __ldg(&g_lut_c[j]) - e * __ldg(&g_lut_s[j]);
}

__global__ void k_build() {          // grid (128, 8), block (32, 8)
    __shared__ __half sh[32][33];
    const int tx = threadIdx.x, ty = threadIdx.y;
    const int n0 = blockIdx.x * 32, k0 = blockIdx.y * 32;
#pragma unroll
    for (int i = 0; i < 4; i++) {
        int kl = ty + i * 8;                       // dct row k' local
        __half h = __float2half(dct_val(n0 + tx, k0 + kl + 1));
        // B1 (GEMM1 B = Cs): tile = n>>6, row = k', kcol = n&63
        int n = n0 + tx, row = k0 + kl;
        g_B1[(size_t)(n >> 6) * TB_EL + tile_off(row, n & 63)] = h;
        sh[kl][tx] = h;
    }
    __syncthreads();
#pragma unroll
    for (int i = 0; i < 4; i++) {
        int nl = ty + i * 8;
        int n = n0 + nl, kp = k0 + tx;             // tx contiguous over k' now
        // B2 (GEMM2 B = Cs^T): tile = (n>>8)*4 + (kp>>6), row = n&255, kcol = kp&63
        g_B2[(size_t)((n >> 8) * 4 + (kp >> 6)) * TB_EL + tile_off(n & 255, kp & 63)]
            = sh[tx][nl];
    }
}

__global__ void k_rho_h(const float* __restrict__ rho) {
    int i = blockIdx.x * 256 + threadIdx.x;        // float4 index
    int m = i >> 10, k = (i & 1023) * 4;
    float4 v = *(const float4*)(rho + (size_t)i * 4);
    __half2 p0 = __floats2half2_rn(v.x, v.y);
    __half2 p1 = __floats2half2_rn(v.z, v.w);
    uint2 u;
    u.x = *(const uint32_t*)&p0;
    u.y = *(const uint32_t*)&p1;
    size_t tb = (size_t)((m >> 7) * 64 + (k >> 6)) * TA_EL;
    *(uint2*)(g_A1 + tb + tile_off(m & 127, k & 63)) = u;   // 8B inside one 16B unit
}

// --------------- HMMA GEMM: out[M,N] = A[M,K] @ B[N,K]^T --------------------
// CTA tile 128x256, 512 threads (16 warps 4x4), warp tile 32x64.
// K-chunk 64, NC=4, 3-stage cp.async.bulk ring with mbarrier completion.
#define STAGE_B (16384 + 32768)         // 49152 B per stage
#define SMEM_SZ (1024 + 3 * STAGE_B)    // 148480

__global__ void __launch_bounds__(512, 1) k_gemm(
    const __half* __restrict__ A, const __half* __restrict__ B,
    float* __restrict__ out, int nkc_a, int nkc_b, int ldo, long long zstride)
{
    extern __shared__ char smem[];
    const uint32_t sb = smem_u32(smem);
    const int tid = threadIdx.x;
    const int lane = tid & 31;
    const int wid = tid >> 5;
    const int warp_m = wid & 3;
    const int warp_n = wid >> 2;
    const int z = blockIdx.z;
    const __half* Abase = A + ((size_t)blockIdx.x * nkc_a + z * 4) * TA_EL;
    const __half* Bbase = B + ((size_t)blockIdx.y * nkc_b + z * 4) * TB_EL;
    out += (long long)z * zstride;

    if (tid == 0) {
        MBARRIER_INIT(sb + 0, 1);
        MBARRIER_INIT(sb + 8, 1);
        MBARRIER_INIT(sb + 16, 1);
    }
    __syncthreads();
    if (tid == 0) {
#pragma unroll
        for (int p = 0; p < 2; p++) {
            uint32_t dst = sb + 1024 + p * STAGE_B;
            MBARRIER_EXPECT_TX(sb + p * 8, STAGE_B);
            BULK_G2S(dst,         Abase + (size_t)p * TA_EL, 16384, sb + p * 8);
            BULK_G2S(dst + 16384, Bbase + (size_t)p * TB_EL, 32768, sb + p * 8);
        }
    }

    float acc[2][8][4];
#pragma unroll
    for (int mt = 0; mt < 2; mt++)
#pragma unroll
        for (int j = 0; j < 8; j++)
#pragma unroll
            for (int q = 0; q < 4; q++) acc[mt][j][q] = 0.f;

    const int a_row = (lane & 7) + ((lane >> 3) & 1) * 8;   // 0..15
    const int a_c   = lane >> 4;                            // 0..1 (16B half)
    const int b_row = (lane & 7) + (lane >> 4) * 8;         // 0..15
    const int b_c   = (lane >> 3) & 1;

#pragma unroll
    for (int i = 0; i < 4; i++) {
        MBARRIER_WAIT_PARITY(sb + (i % 3) * 8, (i / 3) & 1);
        __syncthreads();                     // stage (i+2)%3 fully consumed at i-1
        if (tid == 0 && i + 2 < 4) {
            int s2 = (i + 2) % 3;
            uint32_t dst = sb + 1024 + s2 * STAGE_B;
            MBARRIER_EXPECT_TX(sb + s2 * 8, STAGE_B);
            BULK_G2S(dst,         Abase + (size_t)(i + 2) * TA_EL, 16384, sb + s2 * 8);
            BULK_G2S(dst + 16384, Bbase + (size_t)(i + 2) * TB_EL, 32768, sb + s2 * 8);
        }

        const uint32_t st = sb + 1024 + (uint32_t)(i % 3) * STAGE_B;
#pragma unroll
        for (int s = 0; s < 4; s++) {        // 4 k16 steps per 64-chunk
            uint32_t ah[2][4];
#pragma unroll
            for (int mt = 0; mt < 2; mt++) {
                int r = warp_m * 32 + mt * 16 + a_row;
                int u = s * 2 + a_c;
                LDSM4(ah[mt], st + (uint32_t)(r * 128 + ((u ^ (r & 7)) << 4)));
            }
#pragma unroll
            for (int nt = 0; nt < 4; nt++) {
                uint32_t bh[4];
                int r = warp_n * 64 + nt * 16 + b_row;
                int u = s * 2 + b_c;
                LDSM4(bh, st + 16384u + (uint32_t)(r * 128 + ((u ^ (r & 7)) << 4)));
#pragma unroll
                for (int mt = 0; mt < 2; mt++)
#pragma unroll
                    for (int h = 0; h < 2; h++)
                        MMA(acc[mt][nt * 2 + h], ah[mt], bh[h * 2], bh[h * 2 + 1]);
            }
        }
    }

    const int mbase = blockIdx.x * 128 + warp_m * 32;
    const int nbase = blockIdx.y * 256 + warp_n * 64;
#pragma unroll
    for (int mt = 0; mt < 2; mt++)
#pragma unroll
        for (int j = 0; j < 8; j++) {
            float* d = out + (long long)(mbase + mt * 16 + (lane >> 2)) * ldo
                           + nbase + j * 8 + (lane & 3) * 2;
            d[0] = acc[mt][j][0];
            d[1] = acc[mt][j][1];
            d[(long long)ldo * 8]     = acc[mt][j][2];
            d[(long long)ldo * 8 + 1] = acc[mt][j][3];
        }
}

// -------- reduce partials + lam scale -> Al tiled fp16 ----------------------
__global__ void k_reduce(const float* __restrict__ lam) {
    int i = blockIdx.x * 256 + threadIdx.x;        // float4 index over NB*RR/4
    int m = i >> 6, k = (i & 63) * 4;
    float4 s = make_float4(0.f, 0.f, 0.f, 0.f);
#pragma unroll
    for (int z = 0; z < SPLITS; z++) {
        float4 p = *(const float4*)(g_part + (long long)z * NB * RR + i * 4);
        s.x += p.x; s.y += p.y; s.z += p.z; s.w += p.w;
    }
    s.x *= lam[k]; s.y *= lam[k + 1]; s.z *= lam[k + 2]; s.w *= lam[k + 3];
    __half2 q0 = __floats2half2_rn(s.x, s.y);
    __half2 q1 = __floats2half2_rn(s.z, s.w);
    uint2 u;
    u.x = *(const uint32_t*)&q0;
    u.y = *(const uint32_t*)&q1;
    size_t tb = (size_t)((m >> 7) * 4 + (k >> 6)) * TA_EL;
    *(uint2*)(g_A2 + tb + tile_off(m & 127, k & 63)) = u;
}

extern "C" void kernel_launch(void* const* d_in, const int* in_sizes, int n_in,
                              void* d_out, int out_size) {
    const float* rho = (const float*)d_in[0];
    const float* lam = (const float*)d_in[1];
    float* phi = (float*)d_out;
    (void)in_sizes; (void)n_in; (void)out_size;

    __half *pA1, *pB1, *pB2, *pA2;
    float* pPart;
    cudaGetSymbolAddress((void**)&pA1, g_A1);
    cudaGetSymbolAddress((void**)&pB1, g_B1);
    cudaGetSymbolAddress((void**)&pB2, g_B2);
    cudaGetSymbolAddress((void**)&pA2, g_A2);
    cudaGetSymbolAddress((void**)&pPart, g_part);
    cudaFuncSetAttribute(k_gemm, cudaFuncAttributeMaxDynamicSharedMemorySize, SMEM_SZ);

    k_lut<<<64, 256>>>();
    k_build<<<dim3(128, 8), dim3(32, 8)>>>();
    k_rho_h<<<(NB * NG) / 1024, 256>>>(rho);
    // GEMM1: part[z] = rho @ Cs^T  (M=1024, N=256, K=4096, split-K=16 -> 128 CTAs)
    k_gemm<<<dim3(8, 1, SPLITS), 512, SMEM_SZ>>>(pA1, pB1, pPart, 64, 64, RR,
                                                 (long long)NB * RR);
    k_reduce<<<(NB * RR) / 1024, 256>>>(lam);
    // GEMM2: phi = Al @ Cs  (M=1024, N=4096, K=256 -> 128 CTAs)
    k_gemm<<<dim3(8, 16, 1), 512, SMEM_SZ>>>(pA2, pB2, phi, 4, 4, NG, 0);
}

// round 11
// speedup vs baseline: 4.5176x; 1.0059x over previous
#include <cuda_runtime.h>
#include <cuda_fp16.h>
#include <cstdint>

// phi = (lam ⊙ (rho @ Cs^T)) @ Cs, rank-256. B=1024, N=4096, R=256.
// R10: R8 (bulk-copy ring, pre-tiled/pre-swizzled operands, fp16 HMMA)
//      + register-level fragment double-buffering: LDSM for (s+1 / nt+1)
//      issued before the MMAs of the current group, so LDSM latency is
//      off the critical path.

#define NB 1024
#define NG 4096
#define RR 256
#define SPLITS 16
#define TA_EL 8192      // halfs per A tile (128 x 64)
#define TB_EL 16384     // halfs per B tile (256 x 64)

__device__ __align__(16) __half g_A1[NB * NG];     // rho tiled   [8][64]
__device__ __align__(16) __half g_B1[RR * NG];     // Cs tiled    [1][64]
__device__ __align__(16) __half g_B2[NG * RR];     // Cs^T tiled  [16][4]
__device__ __align__(16) __half g_A2[NB * RR];     // Al tiled    [8][4]
__device__ __align__(16) float g_part[SPLITS * NB * RR];
__device__ __align__(16) float g_lut_c[16384];
__device__ __align__(16) float g_lut_s[16384];

// ----------------------------- PTX helpers ---------------------------------
__device__ __forceinline__ uint32_t smem_u32(const void* p) {
    uint32_t a;
    asm("{ .reg .u64 t; cvta.to.shared.u64 t, %1; cvt.u32.u64 %0, t; }" : "=r"(a) : "l"(p));
    return a;
}
#define MBARRIER_INIT(addr, cnt) \
    asm volatile("mbarrier.init.shared.b64 [%0], %1;" :: "r"((uint32_t)(addr)), "r"((uint32_t)(cnt)) : "memory")
#define MBARRIER_EXPECT_TX(addr, bytes) \
    asm volatile("mbarrier.arrive.expect_tx.shared.b64 _, [%0], %1;" \
        :: "r"((uint32_t)(addr)), "r"((uint32_t)(bytes)) : "memory")
#define MBARRIER_WAIT_PARITY(addr, par) do { \
    uint32_t _mb = (uint32_t)(addr), _pa = (uint32_t)(par), _dn; \
    asm volatile("{\n\t.reg .pred p;\n\t" \
        "mbarrier.try_wait.parity.acquire.cta.shared::cta.b64 p, [%1], %2;\n\t" \
        "selp.b32 %0, 1, 0, p;\n\t}" : "=r"(_dn) : "r"(_mb), "r"(_pa) : "memory"); \
    if (!_dn) { \
        asm volatile("{\n\t.reg .pred P1;\n\tWL_%=:\n\t" \
            "mbarrier.try_wait.parity.acquire.cta.shared::cta.b64 P1, [%0], %1, 0x989680;\n\t" \
            "@P1 bra.uni WD_%=;\n\tbra.uni WL_%=;\n\tWD_%=:\n\t}" \
            :: "r"(_mb), "r"(_pa) : "memory"); \
    } } while (0)
#define BULK_G2S(dst, src, bytes, mbar) \
    asm volatile("cp.async.bulk.shared::cluster.global.mbarrier::complete_tx::bytes " \
                 "[%0], [%1], %2, [%3];" \
        :: "r"((uint32_t)(dst)), "l"(src), "r"((uint32_t)(bytes)), "r"((uint32_t)(mbar)) : "memory")
#define LDSM4(r, a) \
    asm volatile("ldmatrix.sync.aligned.m8n8.x4.shared.b16 {%0,%1,%2,%3}, [%4];" \
        : "=r"((r)[0]), "=r"((r)[1]), "=r"((r)[2]), "=r"((r)[3]) : "r"(a))
#define MMA(c, a, b0, b1) \
    asm volatile("mma.sync.aligned.m16n8k16.row.col.f32.f16.f16.f32 " \
        "{%0,%1,%2,%3},{%4,%5,%6,%7},{%8,%9},{%0,%1,%2,%3};" \
        : "+f"((c)[0]), "+f"((c)[1]), "+f"((c)[2]), "+f"((c)[3]) \
        : "r"((a)[0]), "r"((a)[1]), "r"((a)[2]), "r"((a)[3]), "r"(b0), "r"(b1))

// Tile-internal offset (halfs): 64 halfs/row = 128 B; 16B unit u swizzled by row&7.
__device__ __forceinline__ int tile_off(int r, int kcol) {
    int u = kcol >> 3;
    return r * 64 + ((u ^ (r & 7)) << 3) + (kcol & 7);
}

// ------------------------------- LUT + builds -------------------------------
__global__ void k_lut() {
    int j = blockIdx.x * 256 + threadIdx.x;
    float x = (float)j * (1.0f / 8192.0f);
    float sc = sqrtf(2.0f / 4096.0f);
    g_lut_c[j] = cospif(x) * sc;
    g_lut_s[j] = sinpif(x) * sc;
}

#define PI_F  3.14159274101257324f
#define PI_LO (-8.742277657347586e-8f)

__device__ __forceinline__ float dct_val(int n, int kk) {
    float t1 = 2.0f * (float)n + 1.0f;
    float t2 = PI_F * t1;
    float t3 = t2 * (float)kk;
    float th = t3 * (1.0f / 8192.0f);
    int m = (2 * n + 1) * kk;
    float x = (float)m * (1.0f / 8192.0f);
    float e = fmaf(-PI_F, x, th) - PI_LO * x;
    int j = m & 16383;
    return __ldg(&g_lut_c[j]) - e * __ldg(&g_lut_s[j]);
}

__global__ void k_build() {          // grid (128, 8), block (32, 8)
    __shared__ __half sh[32][33];
    const int tx = threadIdx.x, ty = threadIdx.y;
    const int n0 = blockIdx.x * 32, k0 = blockIdx.y * 32;
#pragma unroll
    for (int i = 0; i < 4; i++) {
        int kl = ty + i * 8;
        __half h = __float2half(dct_val(n0 + tx, k0 + kl + 1));
        int n = n0 + tx, row = k0 + kl;
        g_B1[(size_t)(n >> 6) * TB_EL + tile_off(row, n & 63)] = h;
        sh[kl][tx] = h;
    }
    __syncthreads();
#pragma unroll
    for (int i = 0; i < 4; i++) {
        int nl = ty + i * 8;
        int n = n0 + nl, kp = k0 + tx;
        g_B2[(size_t)((n >> 8) * 4 + (kp >> 6)) * TB_EL + tile_off(n & 255, kp & 63)]
            = sh[tx][nl];
    }
}

__global__ void k_rho_h(const float* __restrict__ rho) {
    int i = blockIdx.x * 256 + threadIdx.x;        // float4 index
    int m = i >> 10, k = (i & 1023) * 4;
    float4 v = *(const float4*)(rho + (size_t)i * 4);
    __half2 p0 = __floats2half2_rn(v.x, v.y);
    __half2 p1 = __floats2half2_rn(v.z, v.w);
    uint2 u;
    u.x = *(const uint32_t*)&p0;
    u.y = *(const uint32_t*)&p1;
    size_t tb = (size_t)((m >> 7) * 64 + (k >> 6)) * TA_EL;
    *(uint2*)(g_A1 + tb + tile_off(m & 127, k & 63)) = u;
}

// --------------- HMMA GEMM: out[M,N] = A[M,K] @ B[N,K]^T --------------------
// CTA tile 128x256, 512 threads (16 warps 4x4), warp tile 32x64.
// K-chunk 64, NC=4, 3-stage cp.async.bulk ring, fragment double-buffering.
#define STAGE_B (16384 + 32768)
#define SMEM_SZ (1024 + 3 * STAGE_B)

__global__ void __launch_bounds__(512, 1) k_gemm(
    const __half* __restrict__ A, const __half* __restrict__ B,
    float* __restrict__ out, int nkc_a, int nkc_b, int ldo, long long zstride)
{
    extern __shared__ char smem[];
    const uint32_t sb = smem_u32(smem);
    const int tid = threadIdx.x;
    const int lane = tid & 31;
    const int wid = tid >> 5;
    const int warp_m = wid & 3;
    const int warp_n = wid >> 2;
    const int z = blockIdx.z;
    const __half* Abase = A + ((size_t)blockIdx.x * nkc_a + z * 4) * TA_EL;
    const __half* Bbase = B + ((size_t)blockIdx.y * nkc_b + z * 4) * TB_EL;
    out += (long long)z * zstride;

    if (tid == 0) {
        MBARRIER_INIT(sb + 0, 1);
        MBARRIER_INIT(sb + 8, 1);
        MBARRIER_INIT(sb + 16, 1);
    }
    __syncthreads();
    if (tid == 0) {
#pragma unroll
        for (int p = 0; p < 2; p++) {
            uint32_t dst = sb + 1024 + p * STAGE_B;
            MBARRIER_EXPECT_TX(sb + p * 8, STAGE_B);
            BULK_G2S(dst,         Abase + (size_t)p * TA_EL, 16384, sb + p * 8);
            BULK_G2S(dst + 16384, Bbase + (size_t)p * TB_EL, 32768, sb + p * 8);
        }
    }

    float acc[2][8][4];
#pragma unroll
    for (int mt = 0; mt < 2; mt++)
#pragma unroll
        for (int j = 0; j < 8; j++)
#pragma unroll
            for (int q = 0; q < 4; q++) acc[mt][j][q] = 0.f;

    // ldmatrix lane geometry (precomputed row/swizzle components)
    const int a_row = (lane & 7) + ((lane >> 3) & 1) * 8;
    const int a_c   = lane >> 4;
    const int b_row = (lane & 7) + (lane >> 4) * 8;
    const int b_c   = (lane >> 3) & 1;

#pragma unroll
    for (int i = 0; i < 4; i++) {
        MBARRIER_WAIT_PARITY(sb + (i % 3) * 8, (i / 3) & 1);
        __syncthreads();
        if (tid == 0 && i + 2 < 4) {
            int s2 = (i + 2) % 3;
            uint32_t dst = sb + 1024 + s2 * STAGE_B;
            MBARRIER_EXPECT_TX(sb + s2 * 8, STAGE_B);
            BULK_G2S(dst,         Abase + (size_t)(i + 2) * TA_EL, 16384, sb + s2 * 8);
            BULK_G2S(dst + 16384, Bbase + (size_t)(i + 2) * TB_EL, 32768, sb + s2 * 8);
        }

        const uint32_t stA = sb + 1024 + (uint32_t)(i % 3) * STAGE_B;
        const uint32_t stB = stA + 16384u;

        auto a_addr = [&](int s, int mt) -> uint32_t {
            int r = warp_m * 32 + mt * 16 + a_row;
            int u = s * 2 + a_c;
            return stA + (uint32_t)(r * 128 + ((u ^ (r & 7)) << 4));
        };
        auto b_addr = [&](int s, int nt) -> uint32_t {
            int r = warp_n * 64 + nt * 16 + b_row;
            int u = s * 2 + b_c;
            return stB + (uint32_t)(r * 128 + ((u ^ (r & 7)) << 4));
        };

        // Fragment double buffers: A over s, B over nt.
        uint32_t ah[2][2][4], bh[2][4];
        LDSM4(ah[0][0], a_addr(0, 0));
        LDSM4(ah[0][1], a_addr(0, 1));
        LDSM4(bh[0], b_addr(0, 0));

#pragma unroll
        for (int s = 0; s < 4; s++) {
            if (s < 3) {                       // prefetch next k-step's A frags
                LDSM4(ah[(s + 1) & 1][0], a_addr(s + 1, 0));
                LDSM4(ah[(s + 1) & 1][1], a_addr(s + 1, 1));
            }
#pragma unroll
            for (int nt = 0; nt < 4; nt++) {
                if (nt < 3)                    // prefetch next B frag
                    LDSM4(bh[(nt + 1) & 1], b_addr(s, nt + 1));
                else if (s < 3)
                    LDSM4(bh[(nt + 1) & 1], b_addr(s + 1, 0));
#pragma unroll
                for (int mt = 0; mt < 2; mt++)
#pragma unroll
                    for (int h = 0; h < 2; h++)
                        MMA(acc[mt][nt * 2 + h], ah[s & 1][mt],
                            bh[nt & 1][h * 2], bh[nt & 1][h * 2 + 1]);
            }
        }
    }

    const int mbase = blockIdx.x * 128 + warp_m * 32;
    const int nbase = blockIdx.y * 256 + warp_n * 64;
#pragma unroll
    for (int mt = 0; mt < 2; mt++)
#pragma unroll
        for (int j = 0; j < 8; j++) {
            float* d = out + (long long)(mbase + mt * 16 + (lane >> 2)) * ldo
                           + nbase + j * 8 + (lane & 3) * 2;
            d[0] = acc[mt][j][0];
            d[1] = acc[mt][j][1];
            d[(long long)ldo * 8]     = acc[mt][j][2];
            d[(long long)ldo * 8 + 1] = acc[mt][j][3];
        }
}

// -------- reduce partials + lam scale -> Al tiled fp16 ----------------------
__global__ void k_reduce(const float* __restrict__ lam) {
    int i = blockIdx.x * 256 + threadIdx.x;        // float4 index over NB*RR/4
    int m = i >> 6, k = (i & 63) * 4;
    float4 s = make_float4(0.f, 0.f, 0.f, 0.f);
#pragma unroll
    for (int z = 0; z < SPLITS; z++) {
        float4 p = *(const float4*)(g_part + (long long)z * NB * RR + i * 4);
        s.x += p.x; s.y += p.y; s.z += p.z; s.w += p.w;
    }
    s.x *= lam[k]; s.y *= lam[k + 1]; s.z *= lam[k + 2]; s.w *= lam[k + 3];
    __half2 q0 = __floats2half2_rn(s.x, s.y);
    __half2 q1 = __floats2half2_rn(s.z, s.w);
    uint2 u;
    u.x = *(const uint32_t*)&q0;
    u.y = *(const uint32_t*)&q1;
    size_t tb = (size_t)((m >> 7) * 4 + (k >> 6)) * TA_EL;
    *(uint2*)(g_A2 + tb + tile_off(m & 127, k & 63)) = u;
}

extern "C" void kernel_launch(void* const* d_in, const int* in_sizes, int n_in,
                              void* d_out, int out_size) {
    const float* rho = (const float*)d_in[0];
    const float* lam = (const float*)d_in[1];
    float* phi = (float*)d_out;
    (void)in_sizes; (void)n_in; (void)out_size;

    __half *pA1, *pB1, *pB2, *pA2;
    float* pPart;
    cudaGetSymbolAddress((void**)&pA1, g_A1);
    cudaGetSymbolAddress((void**)&pB1, g_B1);
    cudaGetSymbolAddress((void**)&pB2, g_B2);
    cudaGetSymbolAddress((void**)&pA2, g_A2);
    cudaGetSymbolAddress((void**)&pPart, g_part);
    cudaFuncSetAttribute(k_gemm, cudaFuncAttributeMaxDynamicSharedMemorySize, SMEM_SZ);

    k_lut<<<64, 256>>>();
    k_build<<<dim3(128, 8), dim3(32, 8)>>>();
    k_rho_h<<<(NB * NG) / 1024, 256>>>(rho);
    // GEMM1: part[z] = rho @ Cs^T  (M=1024, N=256, K=4096, split-K=16 -> 128 CTAs)
    k_gemm<<<dim3(8, 1, SPLITS), 512, SMEM_SZ>>>(pA1, pB1, pPart, 64, 64, RR,
                                                 (long long)NB * RR);
    k_reduce<<<(NB * RR) / 1024, 256>>>(lam);
    // GEMM2: phi = Al @ Cs  (M=1024, N=4096, K=256 -> 128 CTAs)
    k_gemm<<<dim3(8, 16, 1), 512, SMEM_SZ>>>(pA2, pB2, phi, 4, 4, NG, 0);
}

// round 13
// speedup vs baseline: 4.7407x; 1.0494x over previous
#include <cuda_runtime.h>
#include <cuda_fp16.h>
#include <cstdint>

// phi = (lam ⊙ (rho @ Cs^T)) @ Cs, rank-256. B=1024, N=4096, R=256.
// R12: 128x128 CTA tile / 256 threads / 32KB stages -> 2 CTAs per SM,
//      256-CTA grids. Latency hiding across co-resident CTAs (R10 showed
//      intra-CTA ILP is not the wall). fp16 HMMA, bulk-copy 3-stage ring.

#define NB 1024
#define NG 4096
#define RR 256
#define SPLITS 16
#define TA_EL 8192      // halfs per A tile (128 x 64)
#define TB_EL 8192      // halfs per B tile (128 x 64)

__device__ __align__(16) __half g_A1[NB * NG];     // rho tiled    [8][64]
__device__ __align__(16) __half g_B1[RR * NG];     // Cs tiled     [2][64]
__device__ __align__(16) __half g_B2[NG * RR];     // Cs^T tiled   [32][4]
__device__ __align__(16) __half g_A2[NB * RR];     // Al tiled     [8][4]
__device__ __align__(16) float g_part[SPLITS * NB * RR];
__device__ __align__(16) float g_lut_c[16384];
__device__ __align__(16) float g_lut_s[16384];

// ----------------------------- PTX helpers ---------------------------------
__device__ __forceinline__ uint32_t smem_u32(const void* p) {
    uint32_t a;
    asm("{ .reg .u64 t; cvta.to.shared.u64 t, %1; cvt.u32.u64 %0, t; }" : "=r"(a) : "l"(p));
    return a;
}
#define MBARRIER_INIT(addr, cnt) \
    asm volatile("mbarrier.init.shared.b64 [%0], %1;" :: "r"((uint32_t)(addr)), "r"((uint32_t)(cnt)) : "memory")
#define MBARRIER_EXPECT_TX(addr, bytes) \
    asm volatile("mbarrier.arrive.expect_tx.shared.b64 _, [%0], %1;" \
        :: "r"((uint32_t)(addr)), "r"((uint32_t)(bytes)) : "memory")
#define MBARRIER_WAIT_PARITY(addr, par) do { \
    uint32_t _mb = (uint32_t)(addr), _pa = (uint32_t)(par), _dn; \
    asm volatile("{\n\t.reg .pred p;\n\t" \
        "mbarrier.try_wait.parity.acquire.cta.shared::cta.b64 p, [%1], %2;\n\t" \
        "selp.b32 %0, 1, 0, p;\n\t}" : "=r"(_dn) : "r"(_mb), "r"(_pa) : "memory"); \
    if (!_dn) { \
        asm volatile("{\n\t.reg .pred P1;\n\tWL_%=:\n\t" \
            "mbarrier.try_wait.parity.acquire.cta.shared::cta.b64 P1, [%0], %1, 0x989680;\n\t" \
            "@P1 bra.uni WD_%=;\n\tbra.uni WL_%=;\n\tWD_%=:\n\t}" \
            :: "r"(_mb), "r"(_pa) : "memory"); \
    } } while (0)
#define BULK_G2S(dst, src, bytes, mbar) \
    asm volatile("cp.async.bulk.shared::cluster.global.mbarrier::complete_tx::bytes " \
                 "[%0], [%1], %2, [%3];" \
        :: "r"((uint32_t)(dst)), "l"(src), "r"((uint32_t)(bytes)), "r"((uint32_t)(mbar)) : "memory")
#define LDSM4(r, a) \
    asm volatile("ldmatrix.sync.aligned.m8n8.x4.shared.b16 {%0,%1,%2,%3}, [%4];" \
        : "=r"((r)[0]), "=r"((r)[1]), "=r"((r)[2]), "=r"((r)[3]) : "r"(a))
#define MMA(c, a, b0, b1) \
    asm volatile("mma.sync.aligned.m16n8k16.row.col.f32.f16.f16.f32 " \
        "{%0,%1,%2,%3},{%4,%5,%6,%7},{%8,%9},{%0,%1,%2,%3};" \
        : "+f"((c)[0]), "+f"((c)[1]), "+f"((c)[2]), "+f"((c)[3]) \
        : "r"((a)[0]), "r"((a)[1]), "r"((a)[2]), "r"((a)[3]), "r"(b0), "r"(b1))

// Tile-internal offset (halfs): 64 halfs/row = 128 B; 16B unit u swizzled by row&7.
__device__ __forceinline__ int tile_off(int r, int kcol) {
    int u = kcol >> 3;
    return r * 64 + ((u ^ (r & 7)) << 3) + (kcol & 7);
}

// ------------------------------- LUT + builds -------------------------------
__global__ void k_lut() {
    int j = blockIdx.x * 256 + threadIdx.x;
    float x = (float)j * (1.0f / 8192.0f);
    float sc = sqrtf(2.0f / 4096.0f);
    g_lut_c[j] = cospif(x) * sc;
    g_lut_s[j] = sinpif(x) * sc;
}

#define PI_F  3.14159274101257324f
#define PI_LO (-8.742277657347586e-8f)

__device__ __forceinline__ float dct_val(int n, int kk) {
    float t1 = 2.0f * (float)n + 1.0f;
    float t2 = PI_F * t1;
    float t3 = t2 * (float)kk;
    float th = t3 * (1.0f / 8192.0f);
    int m = (2 * n + 1) * kk;
    float x = (float)m * (1.0f / 8192.0f);
    float e = fmaf(-PI_F, x, th) - PI_LO * x;
    int j = m & 16383;
    return __ldg(&g_lut_c[j]) - e * __ldg(&g_lut_s[j]);
}

__global__ void k_build() {          // grid (128, 8), block (32, 8)
    __shared__ __half sh[32][33];
    const int tx = threadIdx.x, ty = threadIdx.y;
    const int n0 = blockIdx.x * 32, k0 = blockIdx.y * 32;
#pragma unroll
    for (int i = 0; i < 4; i++) {
        int kl = ty + i * 8;
        __half h = __float2half(dct_val(n0 + tx, k0 + kl + 1));
        int n = n0 + tx, kp = k0 + kl;           // B1 row = DCT index kp, kdim = n
        g_B1[(size_t)((kp >> 7) * 64 + (n >> 6)) * TB_EL + tile_off(kp & 127, n & 63)] = h;
        sh[kl][tx] = h;
    }
    __syncthreads();
#pragma unroll
    for (int i = 0; i < 4; i++) {
        int nl = ty + i * 8;
        int n = n0 + nl, kp = k0 + tx;           // B2 row = n, kdim = kp
        g_B2[(size_t)((n >> 7) * 4 + (kp >> 6)) * TB_EL + tile_off(n & 127, kp & 63)]
            = sh[tx][nl];
    }
}

__global__ void k_rho_h(const float* __restrict__ rho) {
    int i = blockIdx.x * 256 + threadIdx.x;      // float4 index
    int m = i >> 10, k = (i & 1023) * 4;
    float4 v = *(const float4*)(rho + (size_t)i * 4);
    __half2 p0 = __floats2half2_rn(v.x, v.y);
    __half2 p1 = __floats2half2_rn(v.z, v.w);
    uint2 u;
    u.x = *(const uint32_t*)&p0;
    u.y = *(const uint32_t*)&p1;
    size_t tb = (size_t)((m >> 7) * 64 + (k >> 6)) * TA_EL;
    *(uint2*)(g_A1 + tb + tile_off(m & 127, k & 63)) = u;
}

// --------------- HMMA GEMM: out[M,N] = A[M,K] @ B[N,K]^T --------------------
// CTA tile 128x128, 256 threads (8 warps, 4m x 2n), warp tile 32x64.
// K-chunk 64, NC=4, 3-stage bulk-copy ring. 2 CTAs/SM.
#define STAGE_B (16384 + 16384)          // 32 KB
#define SMEM_SZ (1024 + 3 * STAGE_B)     // 99328

__global__ void __launch_bounds__(256, 2) k_gemm(
    const __half* __restrict__ A, const __half* __restrict__ B,
    float* __restrict__ out, int nkc_a, int nkc_b, int ldo, long long zstride)
{
    extern __shared__ char smem[];
    const uint32_t sb = smem_u32(smem);
    const int tid = threadIdx.x;
    const int lane = tid & 31;
    const int wid = tid >> 5;
    const int warp_m = wid & 3;
    const int warp_n = wid >> 2;          // 0..1
    const int z = blockIdx.z;
    const __half* Abase = A + ((size_t)blockIdx.x * nkc_a + z * 4) * TA_EL;
    const __half* Bbase = B + ((size_t)blockIdx.y * nkc_b + z * 4) * TB_EL;
    out += (long long)z * zstride;

    if (tid == 0) {
        MBARRIER_INIT(sb + 0, 1);
        MBARRIER_INIT(sb + 8, 1);
        MBARRIER_INIT(sb + 16, 1);
    }
    __syncthreads();
    if (tid == 0) {
#pragma unroll
        for (int p = 0; p < 2; p++) {
            uint32_t dst = sb + 1024 + p * STAGE_B;
            MBARRIER_EXPECT_TX(sb + p * 8, STAGE_B);
            BULK_G2S(dst,         Abase + (size_t)p * TA_EL, 16384, sb + p * 8);
            BULK_G2S(dst + 16384, Bbase + (size_t)p * TB_EL, 16384, sb + p * 8);
        }
    }

    float acc[2][8][4];
#pragma unroll
    for (int mt = 0; mt < 2; mt++)
#pragma unroll
        for (int j = 0; j < 8; j++)
#pragma unroll
            for (int q = 0; q < 4; q++) acc[mt][j][q] = 0.f;

    const int a_row = (lane & 7) + ((lane >> 3) & 1) * 8;
    const int a_c   = lane >> 4;
    const int b_row = (lane & 7) + (lane >> 4) * 8;
    const int b_c   = (lane >> 3) & 1;

#pragma unroll
    for (int i = 0; i < 4; i++) {
        MBARRIER_WAIT_PARITY(sb + (i % 3) * 8, (i / 3) & 1);
        __syncthreads();
        if (tid == 0 && i + 2 < 4) {
            int s2 = (i + 2) % 3;
            uint32_t dst = sb + 1024 + s2 * STAGE_B;
            MBARRIER_EXPECT_TX(sb + s2 * 8, STAGE_B);
            BULK_G2S(dst,         Abase + (size_t)(i + 2) * TA_EL, 16384, sb + s2 * 8);
            BULK_G2S(dst + 16384, Bbase + (size_t)(i + 2) * TB_EL, 16384, sb + s2 * 8);
        }

        const uint32_t stA = sb + 1024 + (uint32_t)(i % 3) * STAGE_B;
        const uint32_t stB = stA + 16384u;
#pragma unroll
        for (int s = 0; s < 4; s++) {
            uint32_t ah[2][4];
#pragma unroll
            for (int mt = 0; mt < 2; mt++) {
                int r = warp_m * 32 + mt * 16 + a_row;
                int u = s * 2 + a_c;
                LDSM4(ah[mt], stA + (uint32_t)(r * 128 + ((u ^ (r & 7)) << 4)));
            }
#pragma unroll
            for (int nt = 0; nt < 4; nt++) {
                uint32_t bh[4];
                int r = warp_n * 64 + nt * 16 + b_row;
                int u = s * 2 + b_c;
                LDSM4(bh, stB + (uint32_t)(r * 128 + ((u ^ (r & 7)) << 4)));
#pragma unroll
                for (int mt = 0; mt < 2; mt++)
#pragma unroll
                    for (int h = 0; h < 2; h++)
                        MMA(acc[mt][nt * 2 + h], ah[mt], bh[h * 2], bh[h * 2 + 1]);
            }
        }
    }

    const int mbase = blockIdx.x * 128 + warp_m * 32;
    const int nbase = blockIdx.y * 128 + warp_n * 64;
#pragma unroll
    for (int mt = 0; mt < 2; mt++)
#pragma unroll
        for (int j = 0; j < 8; j++) {
            float* d = out + (long long)(mbase + mt * 16 + (lane >> 2)) * ldo
                           + nbase + j * 8 + (lane & 3) * 2;
            d[0] = acc[mt][j][0];
            d[1] = acc[mt][j][1];
            d[(long long)ldo * 8]     = acc[mt][j][2];
            d[(long long)ldo * 8 + 1] = acc[mt][j][3];
        }
}

// -------- reduce partials + lam scale -> Al tiled fp16 ----------------------
__global__ void k_reduce(const float* __restrict__ lam) {
    int i = blockIdx.x * 256 + threadIdx.x;      // float4 index over NB*RR/4
    int m = i >> 6, k = (i & 63) * 4;
    float4 s = make_float4(0.f, 0.f, 0.f, 0.f);
#pragma unroll
    for (int z = 0; z < SPLITS; z++) {
        float4 p = *(const float4*)(g_part + (long long)z * NB * RR + i * 4);
        s.x += p.x; s.y += p.y; s.z += p.z; s.w += p.w;
    }
    s.x *= lam[k]; s.y *= lam[k + 1]; s.z *= lam[k + 2]; s.w *= lam[k + 3];
    __half2 q0 = __floats2half2_rn(s.x, s.y);
    __half2 q1 = __floats2half2_rn(s.z, s.w);
    uint2 u;
    u.x = *(const uint32_t*)&q0;
    u.y = *(const uint32_t*)&q1;
    size_t tb = (size_t)((m >> 7) * 4 + (k >> 6)) * TA_EL;
    *(uint2*)(g_A2 + tb + tile_off(m & 127, k & 63)) = u;
}

extern "C" void kernel_launch(void* const* d_in, const int* in_sizes, int n_in,
                              void* d_out, int out_size) {
    const float* rho = (const float*)d_in[0];
    const float* lam = (const float*)d_in[1];
    float* phi = (float*)d_out;
    (void)in_sizes; (void)n_in; (void)out_size;

    __half *pA1, *pB1, *pB2, *pA2;
    float* pPart;
    cudaGetSymbolAddress((void**)&pA1, g_A1);
    cudaGetSymbolAddress((void**)&pB1, g_B1);
    cudaGetSymbolAddress((void**)&pB2, g_B2);
    cudaGetSymbolAddress((void**)&pA2, g_A2);
    cudaGetSymbolAddress((void**)&pPart, g_part);
    cudaFuncSetAttribute(k_gemm, cudaFuncAttributeMaxDynamicSharedMemorySize, SMEM_SZ);

    k_lut<<<64, 256>>>();
    k_build<<<dim3(128, 8), dim3(32, 8)>>>();
    k_rho_h<<<(NB * NG) / 1024, 256>>>(rho);
    // GEMM1: part[z] = rho @ Cs^T  (M=1024, N=256, K=4096, split-K=16 -> 256 CTAs)
    k_gemm<<<dim3(8, 2, SPLITS), 256, SMEM_SZ>>>(pA1, pB1, pPart, 64, 64, RR,
                                                 (long long)NB * RR);
    k_reduce<<<(NB * RR) / 1024, 256>>>(lam);
    // GEMM2: phi = Al @ Cs  (M=1024, N=4096, K=256 -> 256 CTAs)
    k_gemm<<<dim3(8, 32, 1), 256, SMEM_SZ>>>(pA2, pB2, phi, 4, 4, NG, 0);
}